// round 1
// baseline (speedup 1.0000x reference)
#include <cuda_runtime.h>

#define NN   50000
#define EE   800000
#define DIN  128
#define DD   256
#define DOUT 64

// ---------------- scratch (device globals: no allocations allowed) ----------
__device__ __align__(16) float g_h[NN * DD];     // current hidden state
__device__ __align__(16) float g_hln[NN * DD];   // layernormed hidden
__device__ __align__(16) float g_agg[NN * DD];   // aggregation buffer (reused)
__device__ int g_rowptr[NN + 1];
__device__ int g_cnt[NN];
__device__ int g_fill[NN];
__device__ int g_col[EE];
__device__ unsigned char g_gin[NN];
__device__ unsigned char g_gout[NN];

// ---------------- CSR build --------------------------------------------------
__global__ void k_zero_cnt() {
    int i = blockIdx.x * blockDim.x + threadIdx.x;
    if (i < NN) g_cnt[i] = 0;
}

__global__ void k_hist(const int* __restrict__ ei) {
    int e = blockIdx.x * blockDim.x + threadIdx.x;
    if (e < EE) atomicAdd(&g_cnt[ei[e]], 1);
}

__global__ void k_scan() {
    __shared__ int sh[1024];
    int t = threadIdx.x;
    const int CH = (NN + 1023) / 1024;
    int s0 = t * CH;
    int s = 0;
    for (int i = 0; i < CH; ++i) {
        int idx = s0 + i;
        if (idx < NN) s += g_cnt[idx];
    }
    sh[t] = s;
    __syncthreads();
    for (int off = 1; off < 1024; off <<= 1) {
        int tmp = (t >= off) ? sh[t - off] : 0;
        __syncthreads();
        sh[t] += tmp;
        __syncthreads();
    }
    int run = sh[t] - s;  // exclusive prefix
    for (int i = 0; i < CH; ++i) {
        int idx = s0 + i;
        if (idx < NN) {
            g_rowptr[idx] = run;
            run += g_cnt[idx];
            g_fill[idx] = 0;
        }
    }
    if (t == 0) g_rowptr[NN] = EE;
}

__global__ void k_scatter(const int* __restrict__ ei) {
    int e = blockIdx.x * blockDim.x + threadIdx.x;
    if (e < EE) {
        int u = ei[e];
        int v = ei[EE + e];
        int pos = g_rowptr[u] + atomicAdd(&g_fill[u], 1);
        g_col[pos] = v;
    }
}

// ---------------- LayerNorm (warp per node) ---------------------------------
__global__ void k_ln(const float* __restrict__ in, float* __restrict__ out,
                     const float* __restrict__ gam, const float* __restrict__ bet) {
    int w = (blockIdx.x * blockDim.x + threadIdx.x) >> 5;
    int lane = threadIdx.x & 31;
    if (w >= NN) return;
    const float4* r = (const float4*)(in + (size_t)w * DD);
    float4 a = r[lane * 2], b = r[lane * 2 + 1];
    float s = a.x + a.y + a.z + a.w + b.x + b.y + b.z + b.w;
#pragma unroll
    for (int o = 16; o; o >>= 1) s += __shfl_xor_sync(0xffffffffu, s, o);
    float mean = s * (1.0f / DD);
    float d, sq = 0.f;
    d = a.x - mean; sq += d * d; d = a.y - mean; sq += d * d;
    d = a.z - mean; sq += d * d; d = a.w - mean; sq += d * d;
    d = b.x - mean; sq += d * d; d = b.y - mean; sq += d * d;
    d = b.z - mean; sq += d * d; d = b.w - mean; sq += d * d;
#pragma unroll
    for (int o = 16; o; o >>= 1) sq += __shfl_xor_sync(0xffffffffu, sq, o);
    float rstd = rsqrtf(sq * (1.0f / DD) + 1e-5f);
    const float4* g4 = (const float4*)gam;
    const float4* b4 = (const float4*)bet;
    float4 g0 = g4[lane * 2], g1 = g4[lane * 2 + 1];
    float4 c0 = b4[lane * 2], c1 = b4[lane * 2 + 1];
    float4 o0, o1;
    o0.x = (a.x - mean) * rstd * g0.x + c0.x;
    o0.y = (a.y - mean) * rstd * g0.y + c0.y;
    o0.z = (a.z - mean) * rstd * g0.z + c0.z;
    o0.w = (a.w - mean) * rstd * g0.w + c0.w;
    o1.x = (b.x - mean) * rstd * g1.x + c1.x;
    o1.y = (b.y - mean) * rstd * g1.y + c1.y;
    o1.z = (b.z - mean) * rstd * g1.z + c1.z;
    o1.w = (b.w - mean) * rstd * g1.w + c1.w;
    float4* ow = (float4*)(out + (size_t)w * DD);
    ow[lane * 2] = o0;
    ow[lane * 2 + 1] = o1;
}

// ---------------- aggregations (warp per node, CSR gather) ------------------
__global__ void k_agg_plain() {
    int w = (blockIdx.x * blockDim.x + threadIdx.x) >> 5;
    int lane = threadIdx.x & 31;
    if (w >= NN) return;
    int beg = g_rowptr[w], end = g_rowptr[w + 1];
    float4 a0 = make_float4(0.f, 0.f, 0.f, 0.f);
    float4 a1 = make_float4(0.f, 0.f, 0.f, 0.f);
    for (int p = beg; p < end; ++p) {
        int v = g_col[p];
        const float4* r = (const float4*)(g_hln + (size_t)v * DD);
        float4 x0 = r[lane * 2], x1 = r[lane * 2 + 1];
        a0.x += x0.x; a0.y += x0.y; a0.z += x0.z; a0.w += x0.w;
        a1.x += x1.x; a1.y += x1.y; a1.z += x1.z; a1.w += x1.w;
    }
    float4* o = (float4*)(g_agg + (size_t)w * DD);
    o[lane * 2] = a0;
    o[lane * 2 + 1] = a1;
}

__global__ void k_agg_gated() {
    int w = (blockIdx.x * blockDim.x + threadIdx.x) >> 5;
    int lane = threadIdx.x & 31;
    if (w >= NN) return;
    float4 a0 = make_float4(0.f, 0.f, 0.f, 0.f);
    float4 a1 = make_float4(0.f, 0.f, 0.f, 0.f);
    if (g_gin[w]) {
        int beg = g_rowptr[w], end = g_rowptr[w + 1];
        for (int p = beg; p < end; ++p) {
            int v = g_col[p];
            if (!g_gout[v]) continue;
            const float4* r = (const float4*)(g_hln + (size_t)v * DD);
            float4 x0 = r[lane * 2], x1 = r[lane * 2 + 1];
            a0.x += x0.x; a0.y += x0.y; a0.z += x0.z; a0.w += x0.w;
            a1.x += x1.x; a1.y += x1.y; a1.z += x1.z; a1.w += x1.w;
        }
    }
    float4* o = (float4*)(g_agg + (size_t)w * DD);
    o[lane * 2] = a0;
    o[lane * 2 + 1] = a1;
}

// ---------------- action gates (warp per node) ------------------------------
// forward-exact reduction of the gumbel-softmax straight-through:
// gate = argmax(logits + gumbel) == 0, temperature is argmax-invariant.
__global__ void k_gates(const float* __restrict__ Wir, const float* __restrict__ Wia,
                        const float* __restrict__ bi,
                        const float* __restrict__ Wor, const float* __restrict__ Woa,
                        const float* __restrict__ bo,
                        const float* __restrict__ gum) {
    int w = (blockIdx.x * blockDim.x + threadIdx.x) >> 5;
    int lane = threadIdx.x & 31;
    if (w >= NN) return;
    const float* h = g_hln + (size_t)w * DD;
    const float* a = g_agg + (size_t)w * DD;
    float i0 = 0.f, i1 = 0.f, q0 = 0.f, q1 = 0.f;
#pragma unroll
    for (int j = 0; j < 8; ++j) {
        int f = lane * 8 + j;
        float hv = h[f], av = a[f];
        i0 += hv * Wir[f * 2 + 0] + av * Wia[f * 2 + 0];
        i1 += hv * Wir[f * 2 + 1] + av * Wia[f * 2 + 1];
        q0 += hv * Wor[f * 2 + 0] + av * Woa[f * 2 + 0];
        q1 += hv * Wor[f * 2 + 1] + av * Woa[f * 2 + 1];
    }
#pragma unroll
    for (int o = 16; o; o >>= 1) {
        i0 += __shfl_xor_sync(0xffffffffu, i0, o);
        i1 += __shfl_xor_sync(0xffffffffu, i1, o);
        q0 += __shfl_xor_sync(0xffffffffu, q0, o);
        q1 += __shfl_xor_sync(0xffffffffu, q1, o);
    }
    if (lane == 0) {
        float a0 = i0 + bi[0] + gum[(0 * NN + w) * 2 + 0];
        float a1 = i1 + bi[1] + gum[(0 * NN + w) * 2 + 1];
        g_gin[w] = (a0 >= a1) ? 1 : 0;  // argmax ties -> index 0
        float c0 = q0 + bo[0] + gum[(1 * NN + w) * 2 + 0];
        float c1 = q1 + bo[1] + gum[(1 * NN + w) * 2 + 1];
        g_gout[w] = (c0 >= c1) ? 1 : 0;
    }
}

// ---------------- SGEMM: C = act(A1@W1 [+ A2@W2] + bias) --------------------
// BM=128, BN=64, BK=16, 256 threads, 8x4 microtile per thread.
template <bool RELU, bool DUAL>
__global__ __launch_bounds__(256) void k_gemm(
    const float* __restrict__ A1, const float* __restrict__ W1,
    const float* __restrict__ A2, const float* __restrict__ W2,
    const float* __restrict__ bias, float* __restrict__ C,
    int M, int Nc, int K) {
    __shared__ __align__(16) float As[16][128];
    __shared__ __align__(16) float Bs[16][64];
    int tid = threadIdx.x;
    int rowBase = blockIdx.y * 128;
    int colBase = blockIdx.x * 64;
    int tRow = tid >> 4;   // 0..15 -> rows tRow*8 .. +7
    int tCol = tid & 15;   // 0..15 -> cols tCol*4 .. +3
    float acc[8][4];
#pragma unroll
    for (int i = 0; i < 8; ++i)
#pragma unroll
        for (int j = 0; j < 4; ++j) acc[i][j] = 0.f;

    int nT = (DUAL ? 2 * K : K) >> 4;
    for (int t = 0; t < nT; ++t) {
        const float* A = A1;
        const float* W = W1;
        int kt = t << 4;
        if (DUAL && kt >= K) { A = A2; W = W2; kt -= K; }
        // load A tile (128x16), transposed into As[k][m]
#pragma unroll
        for (int i = 0; i < 2; ++i) {
            int id = tid + (i << 8);
            int r = id >> 2;
            int kc = (id & 3) << 2;
            int grow = rowBase + r;
            float4 v = make_float4(0.f, 0.f, 0.f, 0.f);
            if (grow < M) v = *(const float4*)(A + (size_t)grow * K + kt + kc);
            As[kc + 0][r] = v.x;
            As[kc + 1][r] = v.y;
            As[kc + 2][r] = v.z;
            As[kc + 3][r] = v.w;
        }
        // load B tile (16x64)
        {
            int r = tid >> 4;
            int c = (tid & 15) << 2;
            float4 v = *(const float4*)(W + (size_t)(kt + r) * Nc + colBase + c);
            *(float4*)&Bs[r][c] = v;
        }
        __syncthreads();
#pragma unroll
        for (int k = 0; k < 16; ++k) {
            float4 m0 = *(const float4*)&As[k][tRow << 3];
            float4 m1 = *(const float4*)&As[k][(tRow << 3) + 4];
            float4 n0 = *(const float4*)&Bs[k][tCol << 2];
            float rm[8] = {m0.x, m0.y, m0.z, m0.w, m1.x, m1.y, m1.z, m1.w};
            float rn[4] = {n0.x, n0.y, n0.z, n0.w};
#pragma unroll
            for (int i = 0; i < 8; ++i)
#pragma unroll
                for (int j = 0; j < 4; ++j) acc[i][j] += rm[i] * rn[j];
        }
        __syncthreads();
    }
    int gc = colBase + (tCol << 2);
    float4 bv = *(const float4*)(bias + gc);
#pragma unroll
    for (int i = 0; i < 8; ++i) {
        int grow = rowBase + (tRow << 3) + i;
        if (grow < M) {
            float4 o;
            o.x = acc[i][0] + bv.x;
            o.y = acc[i][1] + bv.y;
            o.z = acc[i][2] + bv.z;
            o.w = acc[i][3] + bv.w;
            if (RELU) {
                o.x = fmaxf(o.x, 0.f);
                o.y = fmaxf(o.y, 0.f);
                o.z = fmaxf(o.z, 0.f);
                o.w = fmaxf(o.w, 0.f);
            }
            *(float4*)(C + (size_t)grow * Nc + gc) = o;
        }
    }
}

// ---------------- launch -----------------------------------------------------
extern "C" void kernel_launch(void* const* d_in, const int* in_sizes, int n_in,
                              void* d_out, int out_size) {
    const float* x     = (const float*)d_in[0];
    const int*   ei    = (const int*)d_in[1];
    const float* gum   = (const float*)d_in[2];
    const float* W_enc = (const float*)d_in[3];
    const float* b_enc = (const float*)d_in[4];
    const float* W_root = (const float*)d_in[5];
    const float* W_agg  = (const float*)d_in[6];
    const float* b_env  = (const float*)d_in[7];
    const float* Wir = (const float*)d_in[8];
    const float* Wia = (const float*)d_in[9];
    const float* bi  = (const float*)d_in[10];
    const float* Wor = (const float*)d_in[11];
    const float* Woa = (const float*)d_in[12];
    const float* bo  = (const float*)d_in[13];
    // d_in[14..16] = Wt_r, Wt_a, b_t: forward-dead (argmax is temperature-invariant)
    const float* ln_g  = (const float*)d_in[17];
    const float* ln_b  = (const float*)d_in[18];
    const float* W_dec = (const float*)d_in[19];
    const float* b_dec = (const float*)d_in[20];
    float* out = (float*)d_out;

    float *ph, *phln, *pagg;
    cudaGetSymbolAddress((void**)&ph, g_h);
    cudaGetSymbolAddress((void**)&phln, g_hln);
    cudaGetSymbolAddress((void**)&pagg, g_agg);

    int wgrid = (NN * 32 + 255) / 256;            // warp-per-node kernels
    dim3 gMain(DD / 64, (NN + 127) / 128);        // 4 x 391
    dim3 gDec(DOUT / 64, (NN + 127) / 128);       // 1 x 391

    // CSR build (per launch; edge_index is an input)
    k_zero_cnt<<<(NN + 255) / 256, 256>>>();
    k_hist<<<(EE + 255) / 256, 256>>>(ei);
    k_scan<<<1, 1024>>>();
    k_scatter<<<(EE + 255) / 256, 256>>>(ei);

    // encoder: h = relu(x @ W_enc + b_enc)
    k_gemm<true, false><<<gMain, 256>>>(x, W_enc, nullptr, nullptr, b_enc, ph,
                                        NN, DD, DIN);

    for (int l = 0; l < 3; ++l) {
        k_ln<<<wgrid, 256>>>(ph, phln, ln_g, ln_b);
        k_agg_plain<<<wgrid, 256>>>();
        k_gates<<<wgrid, 256>>>(Wir, Wia, bi, Wor, Woa, bo,
                                gum + (size_t)l * 2 * NN * 2);
        k_agg_gated<<<wgrid, 256>>>();
        // h = relu(h_ln @ W_root[l] + agg_w @ W_agg[l] + b_env[l])
        k_gemm<true, true><<<gMain, 256>>>(
            phln, W_root + (size_t)l * DD * DD, pagg, W_agg + (size_t)l * DD * DD,
            b_env + (size_t)l * DD, ph, NN, DD, DD);
    }

    k_ln<<<wgrid, 256>>>(ph, phln, ln_g, ln_b);
    k_gemm<false, false><<<gDec, 256>>>(phln, W_dec, nullptr, nullptr, b_dec, out,
                                        NN, DOUT, DD);
}

// round 2
// speedup vs baseline: 1.1733x; 1.1733x over previous
#include <cuda_runtime.h>

#define NN   50000
#define EE   800000
#define DIN  128
#define DD   256
#define DOUT 64

// ---------------- scratch (device globals) ----------------------------------
__device__ __align__(16) float g_h[NN * DD];
__device__ __align__(16) float g_hln[NN * DD];
__device__ __align__(16) float g_agg[NN * DD];
__device__ __align__(16) float g_r4[NN * 4];   // root logit terms (in0,in1,out0,out1)
__device__ __align__(16) float g_z4[NN * 4];   // per-node projected agg contributions
__device__ int g_rowptr[NN + 1];
__device__ int g_cnt[NN];
__device__ int g_fill[NN];
__device__ int g_col[EE];
__device__ unsigned char g_gin[NN];
__device__ unsigned char g_gout[NN];

// ---------------- f32x2 helpers ---------------------------------------------
#define FMA2(d, a, b, c) \
    asm("fma.rn.f32x2 %0, %1, %2, %3;" : "=l"(d) : "l"(a), "l"(b), "l"(c))
#define PK2(d, x) \
    asm("mov.b64 %0, {%1, %2};" : "=l"(d) : "r"(__float_as_uint(x)), "r"(__float_as_uint(x)))
#define UPK2(lo, hi, v) \
    asm("mov.b64 {%0, %1}, %2;" : "=f"(lo), "=f"(hi) : "l"(v))

// ---------------- CSR build --------------------------------------------------
__global__ void k_zero_cnt() {
    int i = blockIdx.x * blockDim.x + threadIdx.x;
    if (i < NN) g_cnt[i] = 0;
}

__global__ void k_hist(const int* __restrict__ ei) {
    int e = blockIdx.x * blockDim.x + threadIdx.x;
    if (e < EE) atomicAdd(&g_cnt[ei[e]], 1);
}

__global__ void k_scan() {
    __shared__ int sh[1024];
    int t = threadIdx.x;
    const int CH = (NN + 1023) / 1024;
    int s0 = t * CH;
    int s = 0;
    for (int i = 0; i < CH; ++i) {
        int idx = s0 + i;
        if (idx < NN) s += g_cnt[idx];
    }
    sh[t] = s;
    __syncthreads();
    for (int off = 1; off < 1024; off <<= 1) {
        int tmp = (t >= off) ? sh[t - off] : 0;
        __syncthreads();
        sh[t] += tmp;
        __syncthreads();
    }
    int run = sh[t] - s;
    for (int i = 0; i < CH; ++i) {
        int idx = s0 + i;
        if (idx < NN) {
            g_rowptr[idx] = run;
            run += g_cnt[idx];
            g_fill[idx] = 0;
        }
    }
    if (t == 0) g_rowptr[NN] = EE;
}

__global__ void k_scatter(const int* __restrict__ ei) {
    int e = blockIdx.x * blockDim.x + threadIdx.x;
    if (e < EE) {
        int u = ei[e];
        int v = ei[EE + e];
        int pos = g_rowptr[u] + atomicAdd(&g_fill[u], 1);
        g_col[pos] = v;
    }
}

// ---------------- LayerNorm (+ fused 8-wide action projection) --------------
template <bool PROJ>
__global__ void k_ln(const float* __restrict__ in, float* __restrict__ out,
                     const float* __restrict__ gam, const float* __restrict__ bet,
                     const float* __restrict__ Wir, const float* __restrict__ Wia,
                     const float* __restrict__ Wor, const float* __restrict__ Woa) {
    int w = (blockIdx.x * blockDim.x + threadIdx.x) >> 5;
    int lane = threadIdx.x & 31;
    if (w >= NN) return;
    const float4* r = (const float4*)(in + (size_t)w * DD);
    float4 a = r[lane * 2], b = r[lane * 2 + 1];
    float s = a.x + a.y + a.z + a.w + b.x + b.y + b.z + b.w;
#pragma unroll
    for (int o = 16; o; o >>= 1) s += __shfl_xor_sync(0xffffffffu, s, o);
    float mean = s * (1.0f / DD);
    float d, sq = 0.f;
    d = a.x - mean; sq += d * d; d = a.y - mean; sq += d * d;
    d = a.z - mean; sq += d * d; d = a.w - mean; sq += d * d;
    d = b.x - mean; sq += d * d; d = b.y - mean; sq += d * d;
    d = b.z - mean; sq += d * d; d = b.w - mean; sq += d * d;
#pragma unroll
    for (int o = 16; o; o >>= 1) sq += __shfl_xor_sync(0xffffffffu, sq, o);
    float rstd = rsqrtf(sq * (1.0f / DD) + 1e-5f);
    const float4* g4 = (const float4*)gam;
    const float4* b4 = (const float4*)bet;
    float4 g0 = g4[lane * 2], g1 = g4[lane * 2 + 1];
    float4 c0 = b4[lane * 2], c1 = b4[lane * 2 + 1];
    float v[8];
    v[0] = (a.x - mean) * rstd * g0.x + c0.x;
    v[1] = (a.y - mean) * rstd * g0.y + c0.y;
    v[2] = (a.z - mean) * rstd * g0.z + c0.z;
    v[3] = (a.w - mean) * rstd * g0.w + c0.w;
    v[4] = (b.x - mean) * rstd * g1.x + c1.x;
    v[5] = (b.y - mean) * rstd * g1.y + c1.y;
    v[6] = (b.z - mean) * rstd * g1.z + c1.z;
    v[7] = (b.w - mean) * rstd * g1.w + c1.w;
    float4* ow = (float4*)(out + (size_t)w * DD);
    ow[lane * 2] = make_float4(v[0], v[1], v[2], v[3]);
    ow[lane * 2 + 1] = make_float4(v[4], v[5], v[6], v[7]);

    if (PROJ) {
        // per-node 8-wide projection: root terms (Wa_*_r) and agg-message terms (Wa_*_a)
        float acc8[8];
#pragma unroll
        for (int t = 0; t < 8; ++t) acc8[t] = 0.f;
        int f0 = lane * 8;
#pragma unroll
        for (int j = 0; j < 8; ++j) {
            int f = f0 + j;
            float x = v[j];
            float2 wir = *(const float2*)&Wir[f * 2];
            float2 wor = *(const float2*)&Wor[f * 2];
            float2 wia = *(const float2*)&Wia[f * 2];
            float2 woa = *(const float2*)&Woa[f * 2];
            acc8[0] += x * wir.x; acc8[1] += x * wir.y;
            acc8[2] += x * wor.x; acc8[3] += x * wor.y;
            acc8[4] += x * wia.x; acc8[5] += x * wia.y;
            acc8[6] += x * woa.x; acc8[7] += x * woa.y;
        }
#pragma unroll
        for (int o = 16; o; o >>= 1)
#pragma unroll
            for (int t = 0; t < 8; ++t)
                acc8[t] += __shfl_xor_sync(0xffffffffu, acc8[t], o);
        if (lane == 0) {
            *(float4*)&g_r4[w * 4] = make_float4(acc8[0], acc8[1], acc8[2], acc8[3]);
            *(float4*)&g_z4[w * 4] = make_float4(acc8[4], acc8[5], acc8[6], acc8[7]);
        }
    }
}

// ---------------- gates: aggregate 4-wide z, compare with gumbel ------------
// forward-exact reduction of hard gumbel-softmax: gate = argmax(logits+g),
// the per-node temperature is argmax-invariant; straight-through == hard fwd.
__global__ void k_gates(const float* __restrict__ bi, const float* __restrict__ bo,
                        const float* __restrict__ gum) {
    int i = blockIdx.x * blockDim.x + threadIdx.x;
    if (i >= NN) return;
    float4 rr = *(const float4*)&g_r4[i * 4];
    float sx = 0.f, sy = 0.f, sz = 0.f, sw = 0.f;
    int beg = g_rowptr[i], end = g_rowptr[i + 1];
    for (int p = beg; p < end; ++p) {
        int v = g_col[p];
        float4 z = *(const float4*)&g_z4[v * 4];
        sx += z.x; sy += z.y; sz += z.z; sw += z.w;
    }
    float in0 = rr.x + sx + bi[0] + gum[i * 2 + 0];
    float in1 = rr.y + sy + bi[1] + gum[i * 2 + 1];
    float ot0 = rr.z + sz + bo[0] + gum[2 * NN + i * 2 + 0];
    float ot1 = rr.w + sw + bo[1] + gum[2 * NN + i * 2 + 1];
    g_gin[i] = (in0 >= in1) ? 1 : 0;
    g_gout[i] = (ot0 >= ot1) ? 1 : 0;
}

// ---------------- gated aggregation (warp per node, CSR gather) -------------
__global__ void k_agg_gated() {
    int w = (blockIdx.x * blockDim.x + threadIdx.x) >> 5;
    int lane = threadIdx.x & 31;
    if (w >= NN) return;
    float4 a0 = make_float4(0.f, 0.f, 0.f, 0.f);
    float4 a1 = make_float4(0.f, 0.f, 0.f, 0.f);
    if (g_gin[w]) {
        int beg = g_rowptr[w], end = g_rowptr[w + 1];
        for (int p = beg; p < end; ++p) {
            int v = g_col[p];
            if (!g_gout[v]) continue;
            const float4* r = (const float4*)(g_hln + (size_t)v * DD);
            float4 x0 = r[lane * 2], x1 = r[lane * 2 + 1];
            a0.x += x0.x; a0.y += x0.y; a0.z += x0.z; a0.w += x0.w;
            a1.x += x1.x; a1.y += x1.y; a1.z += x1.z; a1.w += x1.w;
        }
    }
    float4* o = (float4*)(g_agg + (size_t)w * DD);
    o[lane * 2] = a0;
    o[lane * 2 + 1] = a1;
}

// ---------------- f32x2 SGEMM: C = act(A1@W1 [+ A2@W2] + bias) --------------
// BM=256, BN=64, BK=16; 8 warps; warp tile 32x64; thread tile 8m x 8n;
// accumulators packed along M via fma.rn.f32x2 (2x FFMA-pipe throughput).
template <bool RELU, bool DUAL>
__global__ __launch_bounds__(256, 2) void k_gemm(
    const float* __restrict__ A1, const float* __restrict__ W1,
    const float* __restrict__ A2, const float* __restrict__ W2,
    const float* __restrict__ bias, float* __restrict__ C,
    int M, int Nc, int K) {
    __shared__ __align__(16) float As[16][256];  // [k][m] transposed
    __shared__ __align__(16) float Bs[16][64];   // [k][n] staggered halves
    int tid = threadIdx.x;
    int warp = tid >> 5;
    int lane = tid & 31;
    int lm = lane >> 3;      // 0..3
    int ln = lane & 7;       // 0..7
    int sw = (ln >> 2) & 1;  // stagger select
    int rowBase = blockIdx.y * 256;
    int colBase = blockIdx.x * 64;

    unsigned long long acc[4][8];
#pragma unroll
    for (int i = 0; i < 4; ++i)
#pragma unroll
        for (int j = 0; j < 8; ++j) acc[i][j] = 0ULL;

    int aRow = rowBase + tid;
    int bR = tid >> 4;
    int bQ = tid & 15;
    int bP = (bQ & ~1) | ((bQ & 1) ^ ((bQ >> 3) & 1));  // swap 16B halves of upper groups

    int nT = (DUAL ? 2 * K : K) >> 4;
    for (int t = 0; t < nT; ++t) {
        const float* A = A1;
        const float* W = W1;
        int kt = t << 4;
        if (DUAL && kt >= K) { A = A2; W = W2; kt -= K; }

        float4 a0 = make_float4(0.f, 0.f, 0.f, 0.f), a1 = a0, a2 = a0, a3 = a0;
        if (aRow < M) {
            const float* ap = A + (size_t)aRow * K + kt;
            a0 = *(const float4*)ap;
            a1 = *(const float4*)(ap + 4);
            a2 = *(const float4*)(ap + 8);
            a3 = *(const float4*)(ap + 12);
        }
        float4 bv = *(const float4*)(W + (size_t)(kt + bR) * Nc + colBase + bQ * 4);
        __syncthreads();
        As[0][tid] = a0.x;  As[1][tid] = a0.y;  As[2][tid] = a0.z;  As[3][tid] = a0.w;
        As[4][tid] = a1.x;  As[5][tid] = a1.y;  As[6][tid] = a1.z;  As[7][tid] = a1.w;
        As[8][tid] = a2.x;  As[9][tid] = a2.y;  As[10][tid] = a2.z; As[11][tid] = a2.w;
        As[12][tid] = a3.x; As[13][tid] = a3.y; As[14][tid] = a3.z; As[15][tid] = a3.w;
        *(float4*)&Bs[bR][bP * 4] = bv;
        __syncthreads();

#pragma unroll
        for (int k = 0; k < 16; ++k) {
            const float* ar = &As[k][warp * 32 + lm * 8];
            ulonglong2 pa = *(const ulonglong2*)ar;        // (m0,m1),(m2,m3)
            ulonglong2 pb = *(const ulonglong2*)(ar + 4);  // (m4,m5),(m6,m7)
            float4 b03 = *(const float4*)&Bs[k][(ln * 2 + sw) * 4];
            float4 b47 = *(const float4*)&Bs[k][(ln * 2 + 1 - sw) * 4];
            unsigned long long bd[8];
            PK2(bd[0], b03.x); PK2(bd[1], b03.y); PK2(bd[2], b03.z); PK2(bd[3], b03.w);
            PK2(bd[4], b47.x); PK2(bd[5], b47.y); PK2(bd[6], b47.z); PK2(bd[7], b47.w);
#pragma unroll
            for (int j = 0; j < 8; ++j) {
                FMA2(acc[0][j], pa.x, bd[j], acc[0][j]);
                FMA2(acc[1][j], pa.y, bd[j], acc[1][j]);
                FMA2(acc[2][j], pb.x, bd[j], acc[2][j]);
                FMA2(acc[3][j], pb.y, bd[j], acc[3][j]);
            }
        }
    }

    int nG = colBase + ln * 8;
    float4 bv0 = *(const float4*)(bias + nG);
    float4 bv1 = *(const float4*)(bias + nG + 4);
#pragma unroll
    for (int i = 0; i < 4; ++i) {
        float lo[8], hi[8];
#pragma unroll
        for (int j = 0; j < 8; ++j) UPK2(lo[j], hi[j], acc[i][j]);
        int m0 = rowBase + warp * 32 + lm * 8 + i * 2;
        if (m0 < M) {
            float4 o0 = make_float4(lo[0] + bv0.x, lo[1] + bv0.y, lo[2] + bv0.z, lo[3] + bv0.w);
            float4 o1 = make_float4(lo[4] + bv1.x, lo[5] + bv1.y, lo[6] + bv1.z, lo[7] + bv1.w);
            if (RELU) {
                o0.x = fmaxf(o0.x, 0.f); o0.y = fmaxf(o0.y, 0.f);
                o0.z = fmaxf(o0.z, 0.f); o0.w = fmaxf(o0.w, 0.f);
                o1.x = fmaxf(o1.x, 0.f); o1.y = fmaxf(o1.y, 0.f);
                o1.z = fmaxf(o1.z, 0.f); o1.w = fmaxf(o1.w, 0.f);
            }
            *(float4*)(C + (size_t)m0 * Nc + nG) = o0;
            *(float4*)(C + (size_t)m0 * Nc + nG + 4) = o1;
        }
        if (m0 + 1 < M) {
            float4 o0 = make_float4(hi[0] + bv0.x, hi[1] + bv0.y, hi[2] + bv0.z, hi[3] + bv0.w);
            float4 o1 = make_float4(hi[4] + bv1.x, hi[5] + bv1.y, hi[6] + bv1.z, hi[7] + bv1.w);
            if (RELU) {
                o0.x = fmaxf(o0.x, 0.f); o0.y = fmaxf(o0.y, 0.f);
                o0.z = fmaxf(o0.z, 0.f); o0.w = fmaxf(o0.w, 0.f);
                o1.x = fmaxf(o1.x, 0.f); o1.y = fmaxf(o1.y, 0.f);
                o1.z = fmaxf(o1.z, 0.f); o1.w = fmaxf(o1.w, 0.f);
            }
            *(float4*)(C + (size_t)(m0 + 1) * Nc + nG) = o0;
            *(float4*)(C + (size_t)(m0 + 1) * Nc + nG + 4) = o1;
        }
    }
}

// ---------------- launch -----------------------------------------------------
extern "C" void kernel_launch(void* const* d_in, const int* in_sizes, int n_in,
                              void* d_out, int out_size) {
    const float* x     = (const float*)d_in[0];
    const int*   ei    = (const int*)d_in[1];
    const float* gum   = (const float*)d_in[2];
    const float* W_enc = (const float*)d_in[3];
    const float* b_enc = (const float*)d_in[4];
    const float* W_root = (const float*)d_in[5];
    const float* W_agg  = (const float*)d_in[6];
    const float* b_env  = (const float*)d_in[7];
    const float* Wir = (const float*)d_in[8];
    const float* Wia = (const float*)d_in[9];
    const float* bi  = (const float*)d_in[10];
    const float* Wor = (const float*)d_in[11];
    const float* Woa = (const float*)d_in[12];
    const float* bo  = (const float*)d_in[13];
    // d_in[14..16] = Wt_r, Wt_a, b_t: forward-dead (argmax is temperature-invariant)
    const float* ln_g  = (const float*)d_in[17];
    const float* ln_b  = (const float*)d_in[18];
    const float* W_dec = (const float*)d_in[19];
    const float* b_dec = (const float*)d_in[20];
    float* out = (float*)d_out;

    float *ph, *phln, *pagg;
    cudaGetSymbolAddress((void**)&ph, g_h);
    cudaGetSymbolAddress((void**)&phln, g_hln);
    cudaGetSymbolAddress((void**)&pagg, g_agg);

    int wgrid = (NN * 32 + 255) / 256;       // warp-per-node kernels
    int ngrid = (NN + 255) / 256;            // thread-per-node kernels
    dim3 gMain(DD / 64, (NN + 255) / 256);   // 4 x 196
    dim3 gDec(DOUT / 64, (NN + 255) / 256);  // 1 x 196

    // CSR build (edge_index is a fresh input each call)
    k_zero_cnt<<<ngrid, 256>>>();
    k_hist<<<(EE + 255) / 256, 256>>>(ei);
    k_scan<<<1, 1024>>>();
    k_scatter<<<(EE + 255) / 256, 256>>>(ei);

    // encoder: h = relu(x @ W_enc + b_enc)
    k_gemm<true, false><<<gMain, 256>>>(x, W_enc, nullptr, nullptr, b_enc, ph,
                                        NN, DD, DIN);

    for (int l = 0; l < 3; ++l) {
        k_ln<true><<<wgrid, 256>>>(ph, phln, ln_g, ln_b, Wir, Wia, Wor, Woa);
        k_gates<<<ngrid, 256>>>(bi, bo, gum + (size_t)l * 2 * NN * 2);
        k_agg_gated<<<wgrid, 256>>>();
        k_gemm<true, true><<<gMain, 256>>>(
            phln, W_root + (size_t)l * DD * DD, pagg, W_agg + (size_t)l * DD * DD,
            b_env + (size_t)l * DD, ph, NN, DD, DD);
    }

    k_ln<false><<<wgrid, 256>>>(ph, phln, ln_g, ln_b,
                                nullptr, nullptr, nullptr, nullptr);
    k_gemm<false, false><<<gDec, 256>>>(phln, W_dec, nullptr, nullptr, b_dec, out,
                                        NN, DOUT, DD);
}

// round 4
// speedup vs baseline: 1.1912x; 1.0153x over previous
#include <cuda_runtime.h>
#include <cstdint>

#define NN   50000
#define EE   800000
#define DIN  128
#define DD   256
#define DOUT 64

// ---------------- scratch (device globals) ----------------------------------
__device__ __align__(16) float g_h[NN * DD];
__device__ __align__(16) float g_hln[NN * DD];
__device__ __align__(16) float g_agg[NN * DD];
__device__ __align__(16) float g_r4[NN * 4];
__device__ __align__(16) float g_z4[NN * 4];
__device__ int g_rowptr[NN + 1];
__device__ int g_cnt[NN];
__device__ int g_fill[NN];
__device__ int g_col[EE];
__device__ unsigned char g_gin[NN];
__device__ unsigned char g_gout[NN];

// ---------------- helpers -----------------------------------------------------
__device__ __forceinline__ float tf32_hi(float x) {
    uint32_t r;
    asm("cvt.rn.tf32.f32 %0, %1;" : "=r"(r) : "f"(x));
    return __uint_as_float(r);
}

__device__ __forceinline__ void mma8(float* c, float2 aLo, float2 aHi8, float2 b) {
    // a0=(g,t)=aLo.x  a1=(g+8,t)=aHi8.x  a2=(g,t+4)=aLo.y  a3=(g+8,t+4)=aHi8.y
    asm volatile(
        "mma.sync.aligned.m16n8k8.row.col.f32.tf32.tf32.f32 "
        "{%0,%1,%2,%3}, {%4,%5,%6,%7}, {%8,%9}, {%0,%1,%2,%3};"
        : "+f"(c[0]), "+f"(c[1]), "+f"(c[2]), "+f"(c[3])
        : "r"(__float_as_uint(aLo.x)), "r"(__float_as_uint(aHi8.x)),
          "r"(__float_as_uint(aLo.y)), "r"(__float_as_uint(aHi8.y)),
          "r"(__float_as_uint(b.x)), "r"(__float_as_uint(b.y)));
}

// ---------------- CSR build --------------------------------------------------
__global__ void k_zero_cnt() {
    int i = blockIdx.x * blockDim.x + threadIdx.x;
    if (i < NN) g_cnt[i] = 0;
}
__global__ void k_hist(const int* __restrict__ ei) {
    int e = blockIdx.x * blockDim.x + threadIdx.x;
    if (e < EE) atomicAdd(&g_cnt[ei[e]], 1);
}
__global__ void k_scan() {
    __shared__ int sh[1024];
    int t = threadIdx.x;
    const int CH = (NN + 1023) / 1024;
    int s0 = t * CH;
    int s = 0;
    for (int i = 0; i < CH; ++i) {
        int idx = s0 + i;
        if (idx < NN) s += g_cnt[idx];
    }
    sh[t] = s;
    __syncthreads();
    for (int off = 1; off < 1024; off <<= 1) {
        int tmp = (t >= off) ? sh[t - off] : 0;
        __syncthreads();
        sh[t] += tmp;
        __syncthreads();
    }
    int run = sh[t] - s;
    for (int i = 0; i < CH; ++i) {
        int idx = s0 + i;
        if (idx < NN) {
            g_rowptr[idx] = run;
            run += g_cnt[idx];
            g_fill[idx] = 0;
        }
    }
    if (t == 0) g_rowptr[NN] = EE;
}
__global__ void k_scatter(const int* __restrict__ ei) {
    int e = blockIdx.x * blockDim.x + threadIdx.x;
    if (e < EE) {
        int u = ei[e];
        int v = ei[EE + e];
        int pos = g_rowptr[u] + atomicAdd(&g_fill[u], 1);
        g_col[pos] = v;
    }
}

// ---------------- LayerNorm (+ fused 8-wide action projection) --------------
template <bool PROJ>
__global__ void k_ln(const float* __restrict__ in, float* __restrict__ out,
                     const float* __restrict__ gam, const float* __restrict__ bet,
                     const float* __restrict__ Wir, const float* __restrict__ Wia,
                     const float* __restrict__ Wor, const float* __restrict__ Woa) {
    int w = (blockIdx.x * blockDim.x + threadIdx.x) >> 5;
    int lane = threadIdx.x & 31;
    if (w >= NN) return;
    const float4* r = (const float4*)(in + (size_t)w * DD);
    float4 a = r[lane * 2], b = r[lane * 2 + 1];
    float s = a.x + a.y + a.z + a.w + b.x + b.y + b.z + b.w;
#pragma unroll
    for (int o = 16; o; o >>= 1) s += __shfl_xor_sync(0xffffffffu, s, o);
    float mean = s * (1.0f / DD);
    float d, sq = 0.f;
    d = a.x - mean; sq += d * d; d = a.y - mean; sq += d * d;
    d = a.z - mean; sq += d * d; d = a.w - mean; sq += d * d;
    d = b.x - mean; sq += d * d; d = b.y - mean; sq += d * d;
    d = b.z - mean; sq += d * d; d = b.w - mean; sq += d * d;
#pragma unroll
    for (int o = 16; o; o >>= 1) sq += __shfl_xor_sync(0xffffffffu, sq, o);
    float rstd = rsqrtf(sq * (1.0f / DD) + 1e-5f);
    const float4* g4 = (const float4*)gam;
    const float4* b4 = (const float4*)bet;
    float4 g0 = g4[lane * 2], g1 = g4[lane * 2 + 1];
    float4 c0 = b4[lane * 2], c1 = b4[lane * 2 + 1];
    float v[8];
    v[0] = (a.x - mean) * rstd * g0.x + c0.x;
    v[1] = (a.y - mean) * rstd * g0.y + c0.y;
    v[2] = (a.z - mean) * rstd * g0.z + c0.z;
    v[3] = (a.w - mean) * rstd * g0.w + c0.w;
    v[4] = (b.x - mean) * rstd * g1.x + c1.x;
    v[5] = (b.y - mean) * rstd * g1.y + c1.y;
    v[6] = (b.z - mean) * rstd * g1.z + c1.z;
    v[7] = (b.w - mean) * rstd * g1.w + c1.w;
    float4* ow = (float4*)(out + (size_t)w * DD);
    ow[lane * 2] = make_float4(v[0], v[1], v[2], v[3]);
    ow[lane * 2 + 1] = make_float4(v[4], v[5], v[6], v[7]);

    if (PROJ) {
        float acc8[8];
#pragma unroll
        for (int t = 0; t < 8; ++t) acc8[t] = 0.f;
        int f0 = lane * 8;
#pragma unroll
        for (int j = 0; j < 8; ++j) {
            int f = f0 + j;
            float x = v[j];
            float2 wir = *(const float2*)&Wir[f * 2];
            float2 wor = *(const float2*)&Wor[f * 2];
            float2 wia = *(const float2*)&Wia[f * 2];
            float2 woa = *(const float2*)&Woa[f * 2];
            acc8[0] += x * wir.x; acc8[1] += x * wir.y;
            acc8[2] += x * wor.x; acc8[3] += x * wor.y;
            acc8[4] += x * wia.x; acc8[5] += x * wia.y;
            acc8[6] += x * woa.x; acc8[7] += x * woa.y;
        }
#pragma unroll
        for (int o = 16; o; o >>= 1)
#pragma unroll
            for (int t = 0; t < 8; ++t)
                acc8[t] += __shfl_xor_sync(0xffffffffu, acc8[t], o);
        if (lane == 0) {
            *(float4*)&g_r4[w * 4] = make_float4(acc8[0], acc8[1], acc8[2], acc8[3]);
            *(float4*)&g_z4[w * 4] = make_float4(acc8[4], acc8[5], acc8[6], acc8[7]);
        }
    }
}

// ---------------- gates ------------------------------------------------------
// forward-exact reduction of hard gumbel-softmax: gate = argmax(logits+g);
// per-node temperature is argmax-invariant; straight-through == hard fwd.
__global__ void k_gates(const float* __restrict__ bi, const float* __restrict__ bo,
                        const float* __restrict__ gum) {
    int i = blockIdx.x * blockDim.x + threadIdx.x;
    if (i >= NN) return;
    float4 rr = *(const float4*)&g_r4[i * 4];
    float sx = 0.f, sy = 0.f, sz = 0.f, sw = 0.f;
    int beg = g_rowptr[i], end = g_rowptr[i + 1];
    for (int p = beg; p < end; ++p) {
        int v = g_col[p];
        float4 z = *(const float4*)&g_z4[v * 4];
        sx += z.x; sy += z.y; sz += z.z; sw += z.w;
    }
    float in0 = rr.x + sx + bi[0] + gum[i * 2 + 0];
    float in1 = rr.y + sy + bi[1] + gum[i * 2 + 1];
    float ot0 = rr.z + sz + bo[0] + gum[2 * NN + i * 2 + 0];
    float ot1 = rr.w + sw + bo[1] + gum[2 * NN + i * 2 + 1];
    g_gin[i] = (in0 >= in1) ? 1 : 0;
    g_gout[i] = (ot0 >= ot1) ? 1 : 0;
}

// ---------------- gated aggregation (warp per node, CSR gather) -------------
__global__ void k_agg_gated() {
    int w = (blockIdx.x * blockDim.x + threadIdx.x) >> 5;
    int lane = threadIdx.x & 31;
    if (w >= NN) return;
    float4 a0 = make_float4(0.f, 0.f, 0.f, 0.f);
    float4 a1 = make_float4(0.f, 0.f, 0.f, 0.f);
    if (g_gin[w]) {
        int beg = g_rowptr[w], end = g_rowptr[w + 1];
        for (int p = beg; p < end; ++p) {
            int v = g_col[p];
            if (!g_gout[v]) continue;
            const float4* r = (const float4*)(g_hln + (size_t)v * DD);
            float4 x0 = r[lane * 2], x1 = r[lane * 2 + 1];
            a0.x += x0.x; a0.y += x0.y; a0.z += x0.z; a0.w += x0.w;
            a1.x += x1.x; a1.y += x1.y; a1.z += x1.z; a1.w += x1.w;
        }
    }
    float4* o = (float4*)(g_agg + (size_t)w * DD);
    o[lane * 2] = a0;
    o[lane * 2 + 1] = a1;
}

// ---------------- mma.sync tf32-split GEMM -----------------------------------
// C = act(A1@W1 [+ A2@W2] + bias). fp32 in/out; each operand split hi+lo tf32,
// 3 MMA products (hh, lh, hl) -> ~2^-22 element error (fp32-class).
// BM=128 BN=64 BK=16, 256 thr, 8 warps (4m x 2n), warp tile 32x32.
// smem/buffer (6144 floats): AsHi[0,2048) AsLo[2048,4096) BsHi[4096,5120) BsLo[5120,6144)
//  A layout: float2[(k8*128 + r)*4 + tig] = (A[r][k8*8+tig], A[r][k8*8+tig+4])
//  B layout: float2[(k8*64 + n)*4 + tig]  = (W[k8*8+tig][n], W[k8*8+tig+4][n])
template <bool RELU, bool DUAL>
__global__ __launch_bounds__(256, 2) void k_mma(
    const float* __restrict__ A1, const float* __restrict__ W1, int K1,
    const float* __restrict__ A2, const float* __restrict__ W2,
    const float* __restrict__ bias, float* __restrict__ C,
    int M, int Nc, int nT) {
    __shared__ float sm[12288];
    const int tid = threadIdx.x;
    const int warp = tid >> 5, lane = tid & 31;
    const int gid = lane >> 2, tig = lane & 3;
    const int wm = warp >> 1, wn = warp & 1;
    const int rowBase = blockIdx.y * 128, colBase = blockIdx.x * 64;
    const int nT1 = K1 >> 4;

    float acc[2][4][4];
#pragma unroll
    for (int i = 0; i < 2; ++i)
#pragma unroll
        for (int j = 0; j < 4; ++j)
#pragma unroll
            for (int q = 0; q < 4; ++q) acc[i][j][q] = 0.f;

    const int aR = tid >> 2, aKq = tid & 3;  // A: rows aR, aR+64; k-quad aKq
    const int kB = tid & 15, nqB = tid >> 4; // B: k-row kB, n-quad nqB

    auto gload = [&](int t, float4& x0, float4& x1, float4& xb) {
        const float *A, *W;
        int kt;
        if (!DUAL || t < nT1) { A = A1; W = W1; kt = t << 4; }
        else { A = A2; W = W2; kt = (t - nT1) << 4; }
        int r0 = rowBase + aR, r1 = r0 + 64;
        x0 = (r0 < M) ? *(const float4*)(A + (size_t)r0 * K1 + kt + aKq * 4)
                      : make_float4(0.f, 0.f, 0.f, 0.f);
        x1 = (r1 < M) ? *(const float4*)(A + (size_t)r1 * K1 + kt + aKq * 4)
                      : make_float4(0.f, 0.f, 0.f, 0.f);
        xb = *(const float4*)(W + (size_t)(kt + kB) * Nc + colBase + nqB * 4);
    };

    auto sts = [&](int buf, const float4& x0, const float4& x1, const float4& xb) {
        float* S = sm + buf * 6144;
        int k8 = aKq >> 1, comp = aKq & 1;
        int base = ((k8 * 128 + aR) * 4) * 2 + comp;
        const float* v = &x0.x;
#pragma unroll
        for (int e = 0; e < 4; ++e) {
            float hi = tf32_hi(v[e]);
            S[base + e * 2] = hi;
            S[2048 + base + e * 2] = tf32_hi(v[e] - hi);
        }
        base = ((k8 * 128 + aR + 64) * 4) * 2 + comp;
        v = &x1.x;
#pragma unroll
        for (int e = 0; e < 4; ++e) {
            float hi = tf32_hi(v[e]);
            S[base + e * 2] = hi;
            S[2048 + base + e * 2] = tf32_hi(v[e] - hi);
        }
        int k8b = kB >> 3, t4 = kB & 3, compb = (kB >> 2) & 1;
        base = 4096 + ((k8b * 64 + nqB * 4) * 4 + t4) * 2 + compb;
        v = &xb.x;
#pragma unroll
        for (int e = 0; e < 4; ++e) {
            float hi = tf32_hi(v[e]);
            S[base + e * 8] = hi;
            S[1024 + base + e * 8] = tf32_hi(v[e] - hi);
        }
    };

    auto compute = [&](int buf) {
        const float2* AH = (const float2*)(sm + buf * 6144);
        const float2* AL = AH + 1024;
        const float2* BH = AH + 2048;
        const float2* BL = AH + 2560;
#pragma unroll
        for (int kk = 0; kk < 2; ++kk) {
            float2 ah[2][2], al[2][2], bh[4], bl[4];
#pragma unroll
            for (int mt = 0; mt < 2; ++mt) {
                int i0 = (kk * 128 + wm * 32 + mt * 16 + gid) * 4 + tig;
                ah[mt][0] = AH[i0];
                ah[mt][1] = AH[i0 + 32];
                al[mt][0] = AL[i0];
                al[mt][1] = AL[i0 + 32];
            }
#pragma unroll
            for (int nt = 0; nt < 4; ++nt) {
                int i0 = (kk * 64 + wn * 32 + nt * 8 + gid) * 4 + tig;
                bh[nt] = BH[i0];
                bl[nt] = BL[i0];
            }
#pragma unroll
            for (int mt = 0; mt < 2; ++mt)
#pragma unroll
                for (int nt = 0; nt < 4; ++nt) {
                    mma8(acc[mt][nt], ah[mt][0], ah[mt][1], bh[nt]);
                    mma8(acc[mt][nt], al[mt][0], al[mt][1], bh[nt]);
                    mma8(acc[mt][nt], ah[mt][0], ah[mt][1], bl[nt]);
                }
        }
    };

    float4 c0, c1, cb;
    gload(0, c0, c1, cb);
    sts(0, c0, c1, cb);
    __syncthreads();
    for (int t = 0; t < nT; ++t) {
        float4 n0, n1, nb;
        bool more = (t + 1 < nT);
        if (more) gload(t + 1, n0, n1, nb);
        compute(t & 1);
        if (more) sts((t + 1) & 1, n0, n1, nb);
        __syncthreads();
    }

#pragma unroll
    for (int mt = 0; mt < 2; ++mt) {
        int r0 = rowBase + wm * 32 + mt * 16 + gid;
#pragma unroll
        for (int nt = 0; nt < 4; ++nt) {
            int col = colBase + wn * 32 + nt * 8 + tig * 2;
            float2 bv = *(const float2*)(bias + col);
            float* a = acc[mt][nt];
            if (r0 < M) {
                float2 o = make_float2(a[0] + bv.x, a[1] + bv.y);
                if (RELU) { o.x = fmaxf(o.x, 0.f); o.y = fmaxf(o.y, 0.f); }
                *(float2*)(C + (size_t)r0 * Nc + col) = o;
            }
            if (r0 + 8 < M) {
                float2 o = make_float2(a[2] + bv.x, a[3] + bv.y);
                if (RELU) { o.x = fmaxf(o.x, 0.f); o.y = fmaxf(o.y, 0.f); }
                *(float2*)(C + (size_t)(r0 + 8) * Nc + col) = o;
            }
        }
    }
}

// ---------------- launch -----------------------------------------------------
extern "C" void kernel_launch(void* const* d_in, const int* in_sizes, int n_in,
                              void* d_out, int out_size) {
    const float* x = (const float*)d_in[0];
    const int* ei = (const int*)d_in[1];
    const float* gum = (const float*)d_in[2];
    const float* W_enc = (const float*)d_in[3];
    const float* b_enc = (const float*)d_in[4];
    const float* W_root = (const float*)d_in[5];
    const float* W_agg = (const float*)d_in[6];
    const float* b_env = (const float*)d_in[7];
    const float* Wir = (const float*)d_in[8];
    const float* Wia = (const float*)d_in[9];
    const float* bi = (const float*)d_in[10];
    const float* Wor = (const float*)d_in[11];
    const float* Woa = (const float*)d_in[12];
    const float* bo = (const float*)d_in[13];
    // d_in[14..16] = temperature net: forward-dead (argmax is temp-invariant)
    const float* ln_g = (const float*)d_in[17];
    const float* ln_b = (const float*)d_in[18];
    const float* W_dec = (const float*)d_in[19];
    const float* b_dec = (const float*)d_in[20];
    float* out = (float*)d_out;

    float *ph, *phln, *pagg;
    cudaGetSymbolAddress((void**)&ph, g_h);
    cudaGetSymbolAddress((void**)&phln, g_hln);
    cudaGetSymbolAddress((void**)&pagg, g_agg);

    int wgrid = (NN * 32 + 255) / 256;
    int ngrid = (NN + 255) / 256;
    dim3 gMain(DD / 64, (NN + 127) / 128);   // 4 x 391
    dim3 gDec(DOUT / 64, (NN + 127) / 128);  // 1 x 391

    // CSR build (edge_index is a fresh input each call)
    k_zero_cnt<<<ngrid, 256>>>();
    k_hist<<<(EE + 255) / 256, 256>>>(ei);
    k_scan<<<1, 1024>>>();
    k_scatter<<<(EE + 255) / 256, 256>>>(ei);

    // encoder: h = relu(x @ W_enc + b_enc)
    k_mma<true, false><<<gMain, 256>>>(x, W_enc, DIN, nullptr, nullptr,
                                       b_enc, ph, NN, DD, DIN / 16);

    for (int l = 0; l < 3; ++l) {
        k_ln<true><<<wgrid, 256>>>(ph, phln, ln_g, ln_b, Wir, Wia, Wor, Woa);
        k_gates<<<ngrid, 256>>>(bi, bo, gum + (size_t)l * 2 * NN * 2);
        k_agg_gated<<<wgrid, 256>>>();
        // h = relu(hln @ W_root[l] + agg @ W_agg[l] + b_env[l])
        k_mma<true, true><<<gMain, 256>>>(
            phln, W_root + (size_t)l * DD * DD, DD,
            pagg, W_agg + (size_t)l * DD * DD,
            b_env + (size_t)l * DD, ph, NN, DD, 2 * DD / 16);
    }

    k_ln<false><<<wgrid, 256>>>(ph, phln, ln_g, ln_b,
                                nullptr, nullptr, nullptr, nullptr);
    k_mma<false, false><<<gDec, 256>>>(phln, W_dec, DD, nullptr, nullptr,
                                       b_dec, out, NN, DOUT, DD / 16);
}

// round 5
// speedup vs baseline: 1.1940x; 1.0023x over previous
#include <cuda_runtime.h>
#include <cstdint>

#define NN   50000
#define EE   800000
#define DIN  128
#define DD   256
#define DOUT 64

// ---------------- scratch (device globals) ----------------------------------
__device__ __align__(16) float g_h[NN * DD];
__device__ __align__(16) float g_hln[NN * DD];
__device__ __align__(16) float g_agg[NN * DD];
__device__ __align__(16) float g_r4[NN * 4];
__device__ __align__(16) float g_z4[NN * 4];
__device__ int g_rowptr[NN + 1];
__device__ int g_cnt[NN];
__device__ int g_fill[NN];
__device__ int g_col[EE];
__device__ unsigned char g_gin[NN];
__device__ unsigned char g_gout[NN];

// ---------------- helpers -----------------------------------------------------
__device__ __forceinline__ float tf32_hi(float x) {
    uint32_t r;
    asm("cvt.rn.tf32.f32 %0, %1;" : "=r"(r) : "f"(x));
    return __uint_as_float(r);
}

__device__ __forceinline__ void mma8(float* c, float2 aLo, float2 aHi8, float2 b) {
    // a0=(g,t)=aLo.x  a1=(g+8,t)=aHi8.x  a2=(g,t+4)=aLo.y  a3=(g+8,t+4)=aHi8.y
    asm volatile(
        "mma.sync.aligned.m16n8k8.row.col.f32.tf32.tf32.f32 "
        "{%0,%1,%2,%3}, {%4,%5,%6,%7}, {%8,%9}, {%0,%1,%2,%3};"
        : "+f"(c[0]), "+f"(c[1]), "+f"(c[2]), "+f"(c[3])
        : "r"(__float_as_uint(aLo.x)), "r"(__float_as_uint(aHi8.x)),
          "r"(__float_as_uint(aLo.y)), "r"(__float_as_uint(aHi8.y)),
          "r"(__float_as_uint(b.x)), "r"(__float_as_uint(b.y)));
}

// ---------------- CSR build --------------------------------------------------
__global__ void k_zero_cnt() {
    int i = blockIdx.x * blockDim.x + threadIdx.x;
    if (i < NN) g_cnt[i] = 0;
}
__global__ void k_hist(const int* __restrict__ ei) {
    int e = blockIdx.x * blockDim.x + threadIdx.x;
    if (e < EE) atomicAdd(&g_cnt[ei[e]], 1);
}
__global__ void k_scan() {
    __shared__ int sh[1024];
    int t = threadIdx.x;
    const int CH = (NN + 1023) / 1024;
    int s0 = t * CH;
    int s = 0;
    for (int i = 0; i < CH; ++i) {
        int idx = s0 + i;
        if (idx < NN) s += g_cnt[idx];
    }
    sh[t] = s;
    __syncthreads();
    for (int off = 1; off < 1024; off <<= 1) {
        int tmp = (t >= off) ? sh[t - off] : 0;
        __syncthreads();
        sh[t] += tmp;
        __syncthreads();
    }
    int run = sh[t] - s;
    for (int i = 0; i < CH; ++i) {
        int idx = s0 + i;
        if (idx < NN) {
            g_rowptr[idx] = run;
            run += g_cnt[idx];
            g_fill[idx] = 0;
        }
    }
    if (t == 0) g_rowptr[NN] = EE;
}
__global__ void k_scatter(const int* __restrict__ ei) {
    int e = blockIdx.x * blockDim.x + threadIdx.x;
    if (e < EE) {
        int u = ei[e];
        int v = ei[EE + e];
        int pos = g_rowptr[u] + atomicAdd(&g_fill[u], 1);
        g_col[pos] = v;
    }
}

// ---------------- LayerNorm (+ fused 8-wide action projection) --------------
template <bool PROJ>
__global__ void k_ln(const float* __restrict__ in, float* __restrict__ out,
                     const float* __restrict__ gam, const float* __restrict__ bet,
                     const float* __restrict__ Wir, const float* __restrict__ Wia,
                     const float* __restrict__ Wor, const float* __restrict__ Woa) {
    int w = (blockIdx.x * blockDim.x + threadIdx.x) >> 5;
    int lane = threadIdx.x & 31;
    if (w >= NN) return;
    const float4* r = (const float4*)(in + (size_t)w * DD);
    float4 a = r[lane * 2], b = r[lane * 2 + 1];
    float s = a.x + a.y + a.z + a.w + b.x + b.y + b.z + b.w;
#pragma unroll
    for (int o = 16; o; o >>= 1) s += __shfl_xor_sync(0xffffffffu, s, o);
    float mean = s * (1.0f / DD);
    float d, sq = 0.f;
    d = a.x - mean; sq += d * d; d = a.y - mean; sq += d * d;
    d = a.z - mean; sq += d * d; d = a.w - mean; sq += d * d;
    d = b.x - mean; sq += d * d; d = b.y - mean; sq += d * d;
    d = b.z - mean; sq += d * d; d = b.w - mean; sq += d * d;
#pragma unroll
    for (int o = 16; o; o >>= 1) sq += __shfl_xor_sync(0xffffffffu, sq, o);
    float rstd = rsqrtf(sq * (1.0f / DD) + 1e-5f);
    const float4* g4 = (const float4*)gam;
    const float4* b4 = (const float4*)bet;
    float4 g0 = g4[lane * 2], g1 = g4[lane * 2 + 1];
    float4 c0 = b4[lane * 2], c1 = b4[lane * 2 + 1];
    float v[8];
    v[0] = (a.x - mean) * rstd * g0.x + c0.x;
    v[1] = (a.y - mean) * rstd * g0.y + c0.y;
    v[2] = (a.z - mean) * rstd * g0.z + c0.z;
    v[3] = (a.w - mean) * rstd * g0.w + c0.w;
    v[4] = (b.x - mean) * rstd * g1.x + c1.x;
    v[5] = (b.y - mean) * rstd * g1.y + c1.y;
    v[6] = (b.z - mean) * rstd * g1.z + c1.z;
    v[7] = (b.w - mean) * rstd * g1.w + c1.w;
    float4* ow = (float4*)(out + (size_t)w * DD);
    ow[lane * 2] = make_float4(v[0], v[1], v[2], v[3]);
    ow[lane * 2 + 1] = make_float4(v[4], v[5], v[6], v[7]);

    if (PROJ) {
        float acc8[8];
#pragma unroll
        for (int t = 0; t < 8; ++t) acc8[t] = 0.f;
        int f0 = lane * 8;
#pragma unroll
        for (int j = 0; j < 8; ++j) {
            int f = f0 + j;
            float x = v[j];
            float2 wir = *(const float2*)&Wir[f * 2];
            float2 wor = *(const float2*)&Wor[f * 2];
            float2 wia = *(const float2*)&Wia[f * 2];
            float2 woa = *(const float2*)&Woa[f * 2];
            acc8[0] += x * wir.x; acc8[1] += x * wir.y;
            acc8[2] += x * wor.x; acc8[3] += x * wor.y;
            acc8[4] += x * wia.x; acc8[5] += x * wia.y;
            acc8[6] += x * woa.x; acc8[7] += x * woa.y;
        }
#pragma unroll
        for (int o = 16; o; o >>= 1)
#pragma unroll
            for (int t = 0; t < 8; ++t)
                acc8[t] += __shfl_xor_sync(0xffffffffu, acc8[t], o);
        if (lane == 0) {
            *(float4*)&g_r4[w * 4] = make_float4(acc8[0], acc8[1], acc8[2], acc8[3]);
            *(float4*)&g_z4[w * 4] = make_float4(acc8[4], acc8[5], acc8[6], acc8[7]);
        }
    }
}

// ---------------- gates ------------------------------------------------------
// forward-exact reduction of hard gumbel-softmax: gate = argmax(logits+g);
// per-node temperature is argmax-invariant; straight-through == hard fwd.
__global__ void k_gates(const float* __restrict__ bi, const float* __restrict__ bo,
                        const float* __restrict__ gum) {
    int i = blockIdx.x * blockDim.x + threadIdx.x;
    if (i >= NN) return;
    float4 rr = *(const float4*)&g_r4[i * 4];
    float sx = 0.f, sy = 0.f, sz = 0.f, sw = 0.f;
    int beg = g_rowptr[i], end = g_rowptr[i + 1];
    for (int p = beg; p < end; ++p) {
        int v = g_col[p];
        float4 z = *(const float4*)&g_z4[v * 4];
        sx += z.x; sy += z.y; sz += z.z; sw += z.w;
    }
    float in0 = rr.x + sx + bi[0] + gum[i * 2 + 0];
    float in1 = rr.y + sy + bi[1] + gum[i * 2 + 1];
    float ot0 = rr.z + sz + bo[0] + gum[2 * NN + i * 2 + 0];
    float ot1 = rr.w + sw + bo[1] + gum[2 * NN + i * 2 + 1];
    g_gin[i] = (in0 >= in1) ? 1 : 0;
    g_gout[i] = (ot0 >= ot1) ? 1 : 0;
}

// ---------------- gated aggregation (warp per node, CSR gather) -------------
__global__ void k_agg_gated() {
    int w = (blockIdx.x * blockDim.x + threadIdx.x) >> 5;
    int lane = threadIdx.x & 31;
    if (w >= NN) return;
    float4 a0 = make_float4(0.f, 0.f, 0.f, 0.f);
    float4 a1 = make_float4(0.f, 0.f, 0.f, 0.f);
    if (g_gin[w]) {
        int beg = g_rowptr[w], end = g_rowptr[w + 1];
        for (int p = beg; p < end; ++p) {
            int v = g_col[p];
            if (!g_gout[v]) continue;
            const float4* r = (const float4*)(g_hln + (size_t)v * DD);
            float4 x0 = r[lane * 2], x1 = r[lane * 2 + 1];
            a0.x += x0.x; a0.y += x0.y; a0.z += x0.z; a0.w += x0.w;
            a1.x += x1.x; a1.y += x1.y; a1.z += x1.z; a1.w += x1.w;
        }
    }
    float4* o = (float4*)(g_agg + (size_t)w * DD);
    o[lane * 2] = a0;
    o[lane * 2 + 1] = a1;
}

// ---------------- mma.sync tf32-split GEMM -----------------------------------
// C = act(A1@W1 [+ A2@W2] + bias). fp32 in/out; each operand split hi+lo tf32,
// 3 MMA products (hh, lh, hl) -> ~2^-22 element error (fp32-class).
// BM=128 BN=64 BK=16, 256 thr, 8 warps (4m x 2n), warp tile 32x32.
// smem/buffer (6144 floats): AsHi[0,2048) AsLo[2048,4096) BsHi[4096,5120) BsLo[5120,6144)
//  A layout: float2[(k8*128 + r)*4 + tig] = (A[r][k8*8+tig], A[r][k8*8+tig+4])
//  B layout: float2[(k8*64 + n)*4 + tig]  = (W[k8*8+tig][n], W[k8*8+tig+4][n])
template <bool RELU, bool DUAL>
__global__ __launch_bounds__(256, 2) void k_mma(
    const float* __restrict__ A1, const float* __restrict__ W1, int K1,
    const float* __restrict__ A2, const float* __restrict__ W2,
    const float* __restrict__ bias, float* __restrict__ C,
    int M, int Nc, int nT) {
    __shared__ float sm[12288];
    const int tid = threadIdx.x;
    const int warp = tid >> 5, lane = tid & 31;
    const int gid = lane >> 2, tig = lane & 3;
    const int wm = warp >> 1, wn = warp & 1;
    const int rowBase = blockIdx.y * 128, colBase = blockIdx.x * 64;
    const int nT1 = K1 >> 4;

    float acc[2][4][4];
#pragma unroll
    for (int i = 0; i < 2; ++i)
#pragma unroll
        for (int j = 0; j < 4; ++j)
#pragma unroll
            for (int q = 0; q < 4; ++q) acc[i][j][q] = 0.f;

    const int aR = tid >> 2, aKq = tid & 3;  // A: rows aR, aR+64; k-quad aKq
    const int kB = tid & 15, nqB = tid >> 4; // B: k-row kB, n-quad nqB

    auto gload = [&](int t, float4& x0, float4& x1, float4& xb) {
        const float *A, *W;
        int kt;
        if (!DUAL || t < nT1) { A = A1; W = W1; kt = t << 4; }
        else { A = A2; W = W2; kt = (t - nT1) << 4; }
        int r0 = rowBase + aR, r1 = r0 + 64;
        x0 = (r0 < M) ? *(const float4*)(A + (size_t)r0 * K1 + kt + aKq * 4)
                      : make_float4(0.f, 0.f, 0.f, 0.f);
        x1 = (r1 < M) ? *(const float4*)(A + (size_t)r1 * K1 + kt + aKq * 4)
                      : make_float4(0.f, 0.f, 0.f, 0.f);
        xb = *(const float4*)(W + (size_t)(kt + kB) * Nc + colBase + nqB * 4);
    };

    auto sts = [&](int buf, const float4& x0, const float4& x1, const float4& xb) {
        float* S = sm + buf * 6144;
        int k8 = aKq >> 1, comp = aKq & 1;
        int base = ((k8 * 128 + aR) * 4) * 2 + comp;
        const float* v = &x0.x;
#pragma unroll
        for (int e = 0; e < 4; ++e) {
            float hi = tf32_hi(v[e]);
            S[base + e * 2] = hi;
            S[2048 + base + e * 2] = tf32_hi(v[e] - hi);
        }
        base = ((k8 * 128 + aR + 64) * 4) * 2 + comp;
        v = &x1.x;
#pragma unroll
        for (int e = 0; e < 4; ++e) {
            float hi = tf32_hi(v[e]);
            S[base + e * 2] = hi;
            S[2048 + base + e * 2] = tf32_hi(v[e] - hi);
        }
        int k8b = kB >> 3, t4 = kB & 3, compb = (kB >> 2) & 1;
        base = 4096 + ((k8b * 64 + nqB * 4) * 4 + t4) * 2 + compb;
        v = &xb.x;
#pragma unroll
        for (int e = 0; e < 4; ++e) {
            float hi = tf32_hi(v[e]);
            S[base + e * 8] = hi;
            S[1024 + base + e * 8] = tf32_hi(v[e] - hi);
        }
    };

    auto compute = [&](int buf) {
        const float2* AH = (const float2*)(sm + buf * 6144);
        const float2* AL = AH + 1024;
        const float2* BH = AH + 2048;
        const float2* BL = AH + 2560;
#pragma unroll
        for (int kk = 0; kk < 2; ++kk) {
            float2 ah[2][2], al[2][2], bh[4], bl[4];
#pragma unroll
            for (int mt = 0; mt < 2; ++mt) {
                int i0 = (kk * 128 + wm * 32 + mt * 16 + gid) * 4 + tig;
                ah[mt][0] = AH[i0];
                ah[mt][1] = AH[i0 + 32];
                al[mt][0] = AL[i0];
                al[mt][1] = AL[i0 + 32];
            }
#pragma unroll
            for (int nt = 0; nt < 4; ++nt) {
                int i0 = (kk * 64 + wn * 32 + nt * 8 + gid) * 4 + tig;
                bh[nt] = BH[i0];
                bl[nt] = BL[i0];
            }
#pragma unroll
            for (int mt = 0; mt < 2; ++mt)
#pragma unroll
                for (int nt = 0; nt < 4; ++nt) {
                    mma8(acc[mt][nt], ah[mt][0], ah[mt][1], bh[nt]);
                    mma8(acc[mt][nt], al[mt][0], al[mt][1], bh[nt]);
                    mma8(acc[mt][nt], ah[mt][0], ah[mt][1], bl[nt]);
                }
        }
    };

    float4 c0, c1, cb;
    gload(0, c0, c1, cb);
    sts(0, c0, c1, cb);
    __syncthreads();
    for (int t = 0; t < nT; ++t) {
        float4 n0, n1, nb;
        bool more = (t + 1 < nT);
        if (more) gload(t + 1, n0, n1, nb);
        compute(t & 1);
        if (more) sts((t + 1) & 1, n0, n1, nb);
        __syncthreads();
    }

#pragma unroll
    for (int mt = 0; mt < 2; ++mt) {
        int r0 = rowBase + wm * 32 + mt * 16 + gid;
#pragma unroll
        for (int nt = 0; nt < 4; ++nt) {
            int col = colBase + wn * 32 + nt * 8 + tig * 2;
            float2 bv = *(const float2*)(bias + col);
            float* a = acc[mt][nt];
            if (r0 < M) {
                float2 o = make_float2(a[0] + bv.x, a[1] + bv.y);
                if (RELU) { o.x = fmaxf(o.x, 0.f); o.y = fmaxf(o.y, 0.f); }
                *(float2*)(C + (size_t)r0 * Nc + col) = o;
            }
            if (r0 + 8 < M) {
                float2 o = make_float2(a[2] + bv.x, a[3] + bv.y);
                if (RELU) { o.x = fmaxf(o.x, 0.f); o.y = fmaxf(o.y, 0.f); }
                *(float2*)(C + (size_t)(r0 + 8) * Nc + col) = o;
            }
        }
    }
}

// ---------------- launch -----------------------------------------------------
extern "C" void kernel_launch(void* const* d_in, const int* in_sizes, int n_in,
                              void* d_out, int out_size) {
    const float* x = (const float*)d_in[0];
    const int* ei = (const int*)d_in[1];
    const float* gum = (const float*)d_in[2];
    const float* W_enc = (const float*)d_in[3];
    const float* b_enc = (const float*)d_in[4];
    const float* W_root = (const float*)d_in[5];
    const float* W_agg = (const float*)d_in[6];
    const float* b_env = (const float*)d_in[7];
    const float* Wir = (const float*)d_in[8];
    const float* Wia = (const float*)d_in[9];
    const float* bi = (const float*)d_in[10];
    const float* Wor = (const float*)d_in[11];
    const float* Woa = (const float*)d_in[12];
    const float* bo = (const float*)d_in[13];
    // d_in[14..16] = temperature net: forward-dead (argmax is temp-invariant)
    const float* ln_g = (const float*)d_in[17];
    const float* ln_b = (const float*)d_in[18];
    const float* W_dec = (const float*)d_in[19];
    const float* b_dec = (const float*)d_in[20];
    float* out = (float*)d_out;

    float *ph, *phln, *pagg;
    cudaGetSymbolAddress((void**)&ph, g_h);
    cudaGetSymbolAddress((void**)&phln, g_hln);
    cudaGetSymbolAddress((void**)&pagg, g_agg);

    int wgrid = (NN * 32 + 255) / 256;
    int ngrid = (NN + 255) / 256;
    dim3 gMain(DD / 64, (NN + 127) / 128);   // 4 x 391
    dim3 gDec(DOUT / 64, (NN + 127) / 128);  // 1 x 391

    // CSR build (edge_index is a fresh input each call)
    k_zero_cnt<<<ngrid, 256>>>();
    k_hist<<<(EE + 255) / 256, 256>>>(ei);
    k_scan<<<1, 1024>>>();
    k_scatter<<<(EE + 255) / 256, 256>>>(ei);

    // encoder: h = relu(x @ W_enc + b_enc)
    k_mma<true, false><<<gMain, 256>>>(x, W_enc, DIN, nullptr, nullptr,
                                       b_enc, ph, NN, DD, DIN / 16);

    for (int l = 0; l < 3; ++l) {
        k_ln<true><<<wgrid, 256>>>(ph, phln, ln_g, ln_b, Wir, Wia, Wor, Woa);
        k_gates<<<ngrid, 256>>>(bi, bo, gum + (size_t)l * 2 * NN * 2);
        k_agg_gated<<<wgrid, 256>>>();
        // h = relu(hln @ W_root[l] + agg @ W_agg[l] + b_env[l])
        k_mma<true, true><<<gMain, 256>>>(
            phln, W_root + (size_t)l * DD * DD, DD,
            pagg, W_agg + (size_t)l * DD * DD,
            b_env + (size_t)l * DD, ph, NN, DD, 2 * DD / 16);
    }

    k_ln<false><<<wgrid, 256>>>(ph, phln, ln_g, ln_b,
                                nullptr, nullptr, nullptr, nullptr);
    k_mma<false, false><<<gDec, 256>>>(phln, W_dec, DD, nullptr, nullptr,
                                       b_dec, out, NN, DOUT, DD / 16);
}

// round 10
// speedup vs baseline: 1.4575x; 1.2207x over previous
#include <cuda_runtime.h>
#include <cuda_fp16.h>
#include <cstdint>

#define NN   50000
#define EE   800000
#define DIN  128
#define DD   256
#define DOUT 64

// ---------------- scratch (device globals) ----------------------------------
__device__ __align__(16) float g_h[NN * DD];
__device__ __align__(16) float g_hln[NN * DD];
__device__ __align__(16) float g_agg[NN * DD];
__device__ __align__(16) float g_r4[NN * 4];
__device__ __align__(16) float g_z4[NN * 4];
__device__ int g_rowptr[NN + 1];
__device__ int g_cnt[NN];
__device__ int g_fill[NN];
__device__ int g_col[EE];
__device__ unsigned char g_gin[NN];
__device__ unsigned char g_gout[NN];

// ---------------- helpers -----------------------------------------------------
__device__ __forceinline__ void split16(float v, __half& hi, __half& lo) {
    hi = __float2half_rn(v);
    lo = __float2half_rn(v - __half2float(hi));
}

__device__ __forceinline__ void mma16816(float* c, uint32_t a0, uint32_t a1,
                                         uint32_t a2, uint32_t a3,
                                         uint32_t b0, uint32_t b1) {
    asm volatile(
        "mma.sync.aligned.m16n8k16.row.col.f32.f16.f16.f32 "
        "{%0,%1,%2,%3}, {%4,%5,%6,%7}, {%8,%9}, {%0,%1,%2,%3};"
        : "+f"(c[0]), "+f"(c[1]), "+f"(c[2]), "+f"(c[3])
        : "r"(a0), "r"(a1), "r"(a2), "r"(a3), "r"(b0), "r"(b1));
}

// ---------------- CSR build --------------------------------------------------
__global__ void k_zero_cnt() {
    int i = blockIdx.x * blockDim.x + threadIdx.x;
    if (i < NN) g_cnt[i] = 0;
}
__global__ void k_hist(const int* __restrict__ ei) {
    int e = blockIdx.x * blockDim.x + threadIdx.x;
    if (e < EE) atomicAdd(&g_cnt[ei[e]], 1);
}
__global__ void k_scan() {
    __shared__ int sh[1024];
    int t = threadIdx.x;
    const int CH = (NN + 1023) / 1024;
    int s0 = t * CH;
    int s = 0;
    for (int i = 0; i < CH; ++i) {
        int idx = s0 + i;
        if (idx < NN) s += g_cnt[idx];
    }
    sh[t] = s;
    __syncthreads();
    for (int off = 1; off < 1024; off <<= 1) {
        int tmp = (t >= off) ? sh[t - off] : 0;
        __syncthreads();
        sh[t] += tmp;
        __syncthreads();
    }
    int run = sh[t] - s;
    for (int i = 0; i < CH; ++i) {
        int idx = s0 + i;
        if (idx < NN) {
            g_rowptr[idx] = run;
            run += g_cnt[idx];
            g_fill[idx] = 0;
        }
    }
    if (t == 0) g_rowptr[NN] = EE;
}
__global__ void k_scatter(const int* __restrict__ ei) {
    int e = blockIdx.x * blockDim.x + threadIdx.x;
    if (e < EE) {
        int u = ei[e];
        int v = ei[EE + e];
        int pos = g_rowptr[u] + atomicAdd(&g_fill[u], 1);
        g_col[pos] = v;
    }
}

// ---------------- LayerNorm (+ fused 8-wide action projection) --------------
template <bool PROJ>
__global__ void k_ln(const float* __restrict__ in, float* __restrict__ out,
                     const float* __restrict__ gam, const float* __restrict__ bet,
                     const float* __restrict__ Wir, const float* __restrict__ Wia,
                     const float* __restrict__ Wor, const float* __restrict__ Woa) {
    int w = (blockIdx.x * blockDim.x + threadIdx.x) >> 5;
    int lane = threadIdx.x & 31;
    if (w >= NN) return;
    const float4* r = (const float4*)(in + (size_t)w * DD);
    float4 a = r[lane * 2], b = r[lane * 2 + 1];
    float s = a.x + a.y + a.z + a.w + b.x + b.y + b.z + b.w;
#pragma unroll
    for (int o = 16; o; o >>= 1) s += __shfl_xor_sync(0xffffffffu, s, o);
    float mean = s * (1.0f / DD);
    float d, sq = 0.f;
    d = a.x - mean; sq += d * d; d = a.y - mean; sq += d * d;
    d = a.z - mean; sq += d * d; d = a.w - mean; sq += d * d;
    d = b.x - mean; sq += d * d; d = b.y - mean; sq += d * d;
    d = b.z - mean; sq += d * d; d = b.w - mean; sq += d * d;
#pragma unroll
    for (int o = 16; o; o >>= 1) sq += __shfl_xor_sync(0xffffffffu, sq, o);
    float rstd = rsqrtf(sq * (1.0f / DD) + 1e-5f);
    const float4* g4 = (const float4*)gam;
    const float4* b4 = (const float4*)bet;
    float4 g0 = g4[lane * 2], g1 = g4[lane * 2 + 1];
    float4 c0 = b4[lane * 2], c1 = b4[lane * 2 + 1];
    float v[8];
    v[0] = (a.x - mean) * rstd * g0.x + c0.x;
    v[1] = (a.y - mean) * rstd * g0.y + c0.y;
    v[2] = (a.z - mean) * rstd * g0.z + c0.z;
    v[3] = (a.w - mean) * rstd * g0.w + c0.w;
    v[4] = (b.x - mean) * rstd * g1.x + c1.x;
    v[5] = (b.y - mean) * rstd * g1.y + c1.y;
    v[6] = (b.z - mean) * rstd * g1.z + c1.z;
    v[7] = (b.w - mean) * rstd * g1.w + c1.w;
    float4* ow = (float4*)(out + (size_t)w * DD);
    ow[lane * 2] = make_float4(v[0], v[1], v[2], v[3]);
    ow[lane * 2 + 1] = make_float4(v[4], v[5], v[6], v[7]);

    if (PROJ) {
        float acc8[8];
#pragma unroll
        for (int t = 0; t < 8; ++t) acc8[t] = 0.f;
        int f0 = lane * 8;
#pragma unroll
        for (int j = 0; j < 8; ++j) {
            int f = f0 + j;
            float x = v[j];
            float2 wir = *(const float2*)&Wir[f * 2];
            float2 wor = *(const float2*)&Wor[f * 2];
            float2 wia = *(const float2*)&Wia[f * 2];
            float2 woa = *(const float2*)&Woa[f * 2];
            acc8[0] += x * wir.x; acc8[1] += x * wir.y;
            acc8[2] += x * wor.x; acc8[3] += x * wor.y;
            acc8[4] += x * wia.x; acc8[5] += x * wia.y;
            acc8[6] += x * woa.x; acc8[7] += x * woa.y;
        }
#pragma unroll
        for (int o = 16; o; o >>= 1)
#pragma unroll
            for (int t = 0; t < 8; ++t)
                acc8[t] += __shfl_xor_sync(0xffffffffu, acc8[t], o);
        if (lane == 0) {
            *(float4*)&g_r4[w * 4] = make_float4(acc8[0], acc8[1], acc8[2], acc8[3]);
            *(float4*)&g_z4[w * 4] = make_float4(acc8[4], acc8[5], acc8[6], acc8[7]);
        }
    }
}

// ---------------- gates ------------------------------------------------------
// forward-exact reduction of hard gumbel-softmax: gate = argmax(logits+g);
// per-node temperature is argmax-invariant; straight-through == hard fwd.
__global__ void k_gates(const float* __restrict__ bi, const float* __restrict__ bo,
                        const float* __restrict__ gum) {
    int i = blockIdx.x * blockDim.x + threadIdx.x;
    if (i >= NN) return;
    float4 rr = *(const float4*)&g_r4[i * 4];
    float sx = 0.f, sy = 0.f, sz = 0.f, sw = 0.f;
    int beg = g_rowptr[i], end = g_rowptr[i + 1];
    for (int p = beg; p < end; ++p) {
        int v = g_col[p];
        float4 z = *(const float4*)&g_z4[v * 4];
        sx += z.x; sy += z.y; sz += z.z; sw += z.w;
    }
    float in0 = rr.x + sx + bi[0] + gum[i * 2 + 0];
    float in1 = rr.y + sy + bi[1] + gum[i * 2 + 1];
    float ot0 = rr.z + sz + bo[0] + gum[2 * NN + i * 2 + 0];
    float ot1 = rr.w + sw + bo[1] + gum[2 * NN + i * 2 + 1];
    g_gin[i] = (in0 >= in1) ? 1 : 0;
    g_gout[i] = (ot0 >= ot1) ? 1 : 0;
}

// ---------------- gated aggregation (warp per node, CSR gather) -------------
__global__ void k_agg_gated() {
    int w = (blockIdx.x * blockDim.x + threadIdx.x) >> 5;
    int lane = threadIdx.x & 31;
    if (w >= NN) return;
    float4 a0 = make_float4(0.f, 0.f, 0.f, 0.f);
    float4 a1 = make_float4(0.f, 0.f, 0.f, 0.f);
    if (g_gin[w]) {
        int beg = g_rowptr[w], end = g_rowptr[w + 1];
        for (int p = beg; p < end; ++p) {
            int v = g_col[p];
            if (!g_gout[v]) continue;
            const float4* r = (const float4*)(g_hln + (size_t)v * DD);
            float4 x0 = r[lane * 2], x1 = r[lane * 2 + 1];
            a0.x += x0.x; a0.y += x0.y; a0.z += x0.z; a0.w += x0.w;
            a1.x += x1.x; a1.y += x1.y; a1.z += x1.z; a1.w += x1.w;
        }
    }
    float4* o = (float4*)(g_agg + (size_t)w * DD);
    o[lane * 2] = a0;
    o[lane * 2 + 1] = a1;
}

// ---------------- mma.sync fp16-split GEMM ------------------------------------
// C = act(A1@W1 [+ A2@W2] + bias). fp32 in/out; each operand split hi+lo fp16
// (11-bit mantissa), 3 products (hh, lh, hl) -> ~2^-21 element error.
// m16n8k16 doubles MAC/instr vs tf32 m16n8k8 on the legacy HMMA pipe.
// BM=128 BN=64 BK=16, 256 thr, 8 warps (4m x 2n), warp tile 32x32.
//
// smem (half2 units, per buffer of 5888):
//   AH[r][w] at r*18 + w      (w=0..7)   pad 18 -> <=2-way conflicts
//   AL at +2304
//   BH[n][w] at 4608 + n*10 + w  pad 10
//   BL at +640
// word w = tig*2 + kh holds half2 {X[k], X[k+1]}, k = kh*8 + 2*tig.
template <bool RELU, bool DUAL>
__global__ __launch_bounds__(256, 2) void k_mma(
    const float* __restrict__ A1, const float* __restrict__ W1, int K1,
    const float* __restrict__ A2, const float* __restrict__ W2,
    const float* __restrict__ bias, float* __restrict__ C,
    int M, int Nc, int nT) {
    __shared__ __half2 sm[11776];  // 2 buffers x 5888
    const int tid = threadIdx.x;
    const int warp = tid >> 5, lane = tid & 31;
    const int gid = lane >> 2, tig = lane & 3;
    const int wm = warp >> 1, wn = warp & 1;
    const int rowBase = blockIdx.y * 128, colBase = blockIdx.x * 64;
    const int nT1 = K1 >> 4;

    float acc[2][4][4];
#pragma unroll
    for (int i = 0; i < 2; ++i)
#pragma unroll
        for (int j = 0; j < 4; ++j)
#pragma unroll
            for (int q = 0; q < 4; ++q) acc[i][j][q] = 0.f;

    const int aR = tid & 127;  // A row in tile
    const int aKh = tid >> 7;  // k-octet 0/1
    const int bN = tid & 63;   // B col in tile
    const int bKq = tid >> 6;  // k-quad 0..3

    auto gload = [&](int t, float4& x0, float4& x1, float4& xb) {
        const float *A, *W;
        int kt;
        if (!DUAL || t < nT1) { A = A1; W = W1; kt = t << 4; }
        else { A = A2; W = W2; kt = (t - nT1) << 4; }
        int r0 = rowBase + aR;
        if (r0 < M) {
            const float* ap = A + (size_t)r0 * K1 + kt + aKh * 8;
            x0 = *(const float4*)ap;
            x1 = *(const float4*)(ap + 4);
        } else {
            x0 = make_float4(0.f, 0.f, 0.f, 0.f);
            x1 = x0;
        }
        const float* wp = W + (size_t)(kt + bKq * 4) * Nc + colBase + bN;
        xb.x = wp[0];
        xb.y = wp[Nc];
        xb.z = wp[2 * Nc];
        xb.w = wp[3 * Nc];
    };

    auto sts = [&](int buf, const float4& x0, const float4& x1, const float4& xb) {
        __half2* S = sm + buf * 5888;
        float av[8] = {x0.x, x0.y, x0.z, x0.w, x1.x, x1.y, x1.z, x1.w};
#pragma unroll
        for (int t = 0; t < 4; ++t) {
            __half h0, l0, h1, l1;
            split16(av[2 * t], h0, l0);
            split16(av[2 * t + 1], h1, l1);
            int idx = aR * 18 + t * 2 + aKh;
            S[idx] = __halves2half2(h0, h1);
            S[2304 + idx] = __halves2half2(l0, l1);
        }
        float bv[4] = {xb.x, xb.y, xb.z, xb.w};
#pragma unroll
        for (int t = 0; t < 2; ++t) {
            __half h0, l0, h1, l1;
            split16(bv[2 * t], h0, l0);
            split16(bv[2 * t + 1], h1, l1);
            int w8 = ((bKq & 1) * 2 + t) * 2 + (bKq >> 1);
            int idx = 4608 + bN * 10 + w8;
            S[idx] = __halves2half2(h0, h1);
            S[640 + idx] = __halves2half2(l0, l1);
        }
    };

    auto compute = [&](int buf) {
        const __half2* S = sm + buf * 5888;
        uint2 ah[2][2], al[2][2], bh[4], bl[4];
#pragma unroll
        for (int mt = 0; mt < 2; ++mt) {
            int r0 = (wm * 32 + mt * 16 + gid) * 18 + tig * 2;
            ah[mt][0] = *(const uint2*)&S[r0];              // (a0, a2)
            ah[mt][1] = *(const uint2*)&S[r0 + 8 * 18];     // (a1, a3)
            al[mt][0] = *(const uint2*)&S[2304 + r0];
            al[mt][1] = *(const uint2*)&S[2304 + r0 + 8 * 18];
        }
#pragma unroll
        for (int nt = 0; nt < 4; ++nt) {
            int n0 = 4608 + (wn * 32 + nt * 8 + gid) * 10 + tig * 2;
            bh[nt] = *(const uint2*)&S[n0];                 // (b0, b1)
            bl[nt] = *(const uint2*)&S[640 + n0];
        }
#pragma unroll
        for (int mt = 0; mt < 2; ++mt)
#pragma unroll
            for (int nt = 0; nt < 4; ++nt) {
                float* c = acc[mt][nt];
                mma16816(c, ah[mt][0].x, ah[mt][1].x, ah[mt][0].y, ah[mt][1].y,
                         bh[nt].x, bh[nt].y);
                mma16816(c, al[mt][0].x, al[mt][1].x, al[mt][0].y, al[mt][1].y,
                         bh[nt].x, bh[nt].y);
                mma16816(c, ah[mt][0].x, ah[mt][1].x, ah[mt][0].y, ah[mt][1].y,
                         bl[nt].x, bl[nt].y);
            }
    };

    float4 c0, c1, cb;
    gload(0, c0, c1, cb);
    sts(0, c0, c1, cb);
    __syncthreads();
    for (int t = 0; t < nT; ++t) {
        float4 n0, n1, nb;
        bool more = (t + 1 < nT);
        if (more) gload(t + 1, n0, n1, nb);
        compute(t & 1);
        if (more) sts((t + 1) & 1, n0, n1, nb);
        __syncthreads();
    }

#pragma unroll
    for (int mt = 0; mt < 2; ++mt) {
        int r0 = rowBase + wm * 32 + mt * 16 + gid;
#pragma unroll
        for (int nt = 0; nt < 4; ++nt) {
            int col = colBase + wn * 32 + nt * 8 + tig * 2;
            float2 bv = *(const float2*)(bias + col);
            float* a = acc[mt][nt];
            if (r0 < M) {
                float2 o = make_float2(a[0] + bv.x, a[1] + bv.y);
                if (RELU) { o.x = fmaxf(o.x, 0.f); o.y = fmaxf(o.y, 0.f); }
                *(float2*)(C + (size_t)r0 * Nc + col) = o;
            }
            if (r0 + 8 < M) {
                float2 o = make_float2(a[2] + bv.x, a[3] + bv.y);
                if (RELU) { o.x = fmaxf(o.x, 0.f); o.y = fmaxf(o.y, 0.f); }
                *(float2*)(C + (size_t)(r0 + 8) * Nc + col) = o;
            }
        }
    }
}

// ---------------- launch -----------------------------------------------------
extern "C" void kernel_launch(void* const* d_in, const int* in_sizes, int n_in,
                              void* d_out, int out_size) {
    const float* x = (const float*)d_in[0];
    const int* ei = (const int*)d_in[1];
    const float* gum = (const float*)d_in[2];
    const float* W_enc = (const float*)d_in[3];
    const float* b_enc = (const float*)d_in[4];
    const float* W_root = (const float*)d_in[5];
    const float* W_agg = (const float*)d_in[6];
    const float* b_env = (const float*)d_in[7];
    const float* Wir = (const float*)d_in[8];
    const float* Wia = (const float*)d_in[9];
    const float* bi = (const float*)d_in[10];
    const float* Wor = (const float*)d_in[11];
    const float* Woa = (const float*)d_in[12];
    const float* bo = (const float*)d_in[13];
    // d_in[14..16] = temperature net: forward-dead (argmax is temp-invariant)
    const float* ln_g = (const float*)d_in[17];
    const float* ln_b = (const float*)d_in[18];
    const float* W_dec = (const float*)d_in[19];
    const float* b_dec = (const float*)d_in[20];
    float* out = (float*)d_out;

    float *ph, *phln, *pagg;
    cudaGetSymbolAddress((void**)&ph, g_h);
    cudaGetSymbolAddress((void**)&phln, g_hln);
    cudaGetSymbolAddress((void**)&pagg, g_agg);

    int wgrid = (NN * 32 + 255) / 256;
    int ngrid = (NN + 255) / 256;
    dim3 gMain(DD / 64, (NN + 127) / 128);   // 4 x 391
    dim3 gDec(DOUT / 64, (NN + 127) / 128);  // 1 x 391

    // CSR build (edge_index is a fresh input each call)
    k_zero_cnt<<<ngrid, 256>>>();
    k_hist<<<(EE + 255) / 256, 256>>>(ei);
    k_scan<<<1, 1024>>>();
    k_scatter<<<(EE + 255) / 256, 256>>>(ei);

    // encoder: h = relu(x @ W_enc + b_enc)
    k_mma<true, false><<<gMain, 256>>>(x, W_enc, DIN, nullptr, nullptr,
                                       b_enc, ph, NN, DD, DIN / 16);

    for (int l = 0; l < 3; ++l) {
        k_ln<true><<<wgrid, 256>>>(ph, phln, ln_g, ln_b, Wir, Wia, Wor, Woa);
        k_gates<<<ngrid, 256>>>(bi, bo, gum + (size_t)l * 2 * NN * 2);
        k_agg_gated<<<wgrid, 256>>>();
        // h = relu(hln @ W_root[l] + agg @ W_agg[l] + b_env[l])
        k_mma<true, true><<<gMain, 256>>>(
            phln, W_root + (size_t)l * DD * DD, DD,
            pagg, W_agg + (size_t)l * DD * DD,
            b_env + (size_t)l * DD, ph, NN, DD, 2 * DD / 16);
    }

    k_ln<false><<<wgrid, 256>>>(ph, phln, ln_g, ln_b,
                                nullptr, nullptr, nullptr, nullptr);
    k_mma<false, false><<<gDec, 256>>>(phln, W_dec, DD, nullptr, nullptr,
                                       b_dec, out, NN, DOUT, DD / 16);
}

// round 12
// speedup vs baseline: 1.5017x; 1.0303x over previous
#include <cuda_runtime.h>
#include <cuda_fp16.h>
#include <cstdint>

#define NN   50000
#define EE   800000
#define DIN  128
#define DD   256
#define DOUT 64

// ---------------- scratch (device globals) ----------------------------------
__device__ __align__(16) float g_h[NN * DD];
__device__ __align__(16) float g_hln[NN * DD];
__device__ __align__(16) float g_r4[NN * 4];
__device__ __align__(16) float g_z4[NN * 4];
// fp16 split planes (A operands)
__device__ __align__(16) __half g_xhi[NN * DIN];
__device__ __align__(16) __half g_xlo[NN * DIN];
__device__ __align__(16) __half g_hhi[NN * DD];
__device__ __align__(16) __half g_hlo[NN * DD];
__device__ __align__(16) __half g_ahi[NN * DD];   // compacted agg rows
__device__ __align__(16) __half g_alo[NN * DD];
// W images (half2): [cb][kt][n(64)][k_pair(8)], linear k within tile
#define IMG_ENC 0
#define IMG_ROOT(l) (16384 + (l) * 32768)
#define IMG_AGG(l)  (114688 + (l) * 32768)
#define IMG_DEC 212992
__device__ __align__(16) __half2 g_whi[221184];
__device__ __align__(16) __half2 g_wlo[221184];
// CSR + gates
__device__ int g_rowptr[NN + 1];
__device__ int g_cnt[NN];
__device__ int g_fill[NN];
__device__ int g_col[EE];
__device__ unsigned char g_gin[NN];
__device__ unsigned char g_gout[NN];
__device__ int g_nact;
__device__ int g_list[NN];

// ---------------- helpers -----------------------------------------------------
__device__ __forceinline__ void split8_store(__half* hp, __half* lp, const float* v) {
    __align__(16) __half hs[8];
    __align__(16) __half ls[8];
#pragma unroll
    for (int j = 0; j < 8; ++j) {
        hs[j] = __float2half_rn(v[j]);
        ls[j] = __float2half_rn(v[j] - __half2float(hs[j]));
    }
    *(uint4*)hp = *(const uint4*)hs;
    *(uint4*)lp = *(const uint4*)ls;
}

__device__ __forceinline__ void mma16816(float* c, uint32_t a0, uint32_t a1,
                                         uint32_t a2, uint32_t a3,
                                         uint32_t b0, uint32_t b1) {
    asm volatile(
        "mma.sync.aligned.m16n8k16.row.col.f32.f16.f16.f32 "
        "{%0,%1,%2,%3}, {%4,%5,%6,%7}, {%8,%9}, {%0,%1,%2,%3};"
        : "+f"(c[0]), "+f"(c[1]), "+f"(c[2]), "+f"(c[3])
        : "r"(a0), "r"(a1), "r"(a2), "r"(a3), "r"(b0), "r"(b1));
}

// ---------------- CSR build --------------------------------------------------
__global__ void k_zero_cnt() {
    int i = blockIdx.x * blockDim.x + threadIdx.x;
    if (i < NN) g_cnt[i] = 0;
}
__global__ void k_hist(const int* __restrict__ ei) {
    int e = blockIdx.x * blockDim.x + threadIdx.x;
    if (e < EE) atomicAdd(&g_cnt[ei[e]], 1);
}
__global__ void k_scan() {
    __shared__ int sh[1024];
    int t = threadIdx.x;
    const int CH = (NN + 1023) / 1024;
    int s0 = t * CH;
    int s = 0;
    for (int i = 0; i < CH; ++i) {
        int idx = s0 + i;
        if (idx < NN) s += g_cnt[idx];
    }
    sh[t] = s;
    __syncthreads();
    for (int off = 1; off < 1024; off <<= 1) {
        int tmp = (t >= off) ? sh[t - off] : 0;
        __syncthreads();
        sh[t] += tmp;
        __syncthreads();
    }
    int run = sh[t] - s;
    for (int i = 0; i < CH; ++i) {
        int idx = s0 + i;
        if (idx < NN) {
            g_rowptr[idx] = run;
            run += g_cnt[idx];
            g_fill[idx] = 0;
        }
    }
    if (t == 0) g_rowptr[NN] = EE;
}
__global__ void k_scatter(const int* __restrict__ ei) {
    int e = blockIdx.x * blockDim.x + threadIdx.x;
    if (e < EE) {
        int u = ei[e];
        int v = ei[EE + e];
        int pos = g_rowptr[u] + atomicAdd(&g_fill[u], 1);
        g_col[pos] = v;
    }
}

// ---------------- packing ------------------------------------------------------
// x planes: 8 elems per thread
__global__ void k_pack_x(const float* __restrict__ x) {
    int i = blockIdx.x * blockDim.x + threadIdx.x;
    if (i >= NN * DIN / 8) return;
    const float4* p = (const float4*)x + (size_t)i * 2;
    float4 a = p[0], b = p[1];
    float v[8] = {a.x, a.y, a.z, a.w, b.x, b.y, b.z, b.w};
    split8_store(g_xhi + (size_t)i * 8, g_xlo + (size_t)i * 8, v);
}

// W image: i = ((cb*nKt + kt)*64 + n)*8 + s, s = k-pair in tile
__global__ void k_pack_w(const float* __restrict__ W, int K, int N, int base) {
    int i = blockIdx.x * blockDim.x + threadIdx.x;
    if (i >= K * N / 2) return;
    int s = i & 7;
    int n = (i >> 3) & 63;
    int rest = i >> 9;
    int nKt = K >> 4;
    int kt = rest % nKt, cb = rest / nKt;
    int k0 = kt * 16 + s * 2;
    int ng = cb * 64 + n;
    float v0 = W[(size_t)k0 * N + ng];
    float v1 = W[(size_t)(k0 + 1) * N + ng];
    __half h0 = __float2half_rn(v0), h1 = __float2half_rn(v1);
    __half l0 = __float2half_rn(v0 - __half2float(h0));
    __half l1 = __float2half_rn(v1 - __half2float(h1));
    g_whi[base + i] = __halves2half2(h0, h1);
    g_wlo[base + i] = __halves2half2(l0, l1);
}

// ---------------- LayerNorm (+ proj, + plane writes) --------------------------
template <bool PROJ>
__global__ void k_ln(const float* __restrict__ in,
                     const float* __restrict__ gam, const float* __restrict__ bet,
                     const float* __restrict__ Wir, const float* __restrict__ Wia,
                     const float* __restrict__ Wor, const float* __restrict__ Woa) {
    if (PROJ && blockIdx.x == 0 && threadIdx.x == 0) g_nact = 0;
    int w = (blockIdx.x * blockDim.x + threadIdx.x) >> 5;
    int lane = threadIdx.x & 31;
    if (w >= NN) return;
    const float4* r = (const float4*)(in + (size_t)w * DD);
    float4 a = r[lane * 2], b = r[lane * 2 + 1];
    float s = a.x + a.y + a.z + a.w + b.x + b.y + b.z + b.w;
#pragma unroll
    for (int o = 16; o; o >>= 1) s += __shfl_xor_sync(0xffffffffu, s, o);
    float mean = s * (1.0f / DD);
    float d, sq = 0.f;
    d = a.x - mean; sq += d * d; d = a.y - mean; sq += d * d;
    d = a.z - mean; sq += d * d; d = a.w - mean; sq += d * d;
    d = b.x - mean; sq += d * d; d = b.y - mean; sq += d * d;
    d = b.z - mean; sq += d * d; d = b.w - mean; sq += d * d;
#pragma unroll
    for (int o = 16; o; o >>= 1) sq += __shfl_xor_sync(0xffffffffu, sq, o);
    float rstd = rsqrtf(sq * (1.0f / DD) + 1e-5f);
    const float4* g4 = (const float4*)gam;
    const float4* b4 = (const float4*)bet;
    float4 g0 = g4[lane * 2], g1 = g4[lane * 2 + 1];
    float4 c0 = b4[lane * 2], c1 = b4[lane * 2 + 1];
    float v[8];
    v[0] = (a.x - mean) * rstd * g0.x + c0.x;
    v[1] = (a.y - mean) * rstd * g0.y + c0.y;
    v[2] = (a.z - mean) * rstd * g0.z + c0.z;
    v[3] = (a.w - mean) * rstd * g0.w + c0.w;
    v[4] = (b.x - mean) * rstd * g1.x + c1.x;
    v[5] = (b.y - mean) * rstd * g1.y + c1.y;
    v[6] = (b.z - mean) * rstd * g1.z + c1.z;
    v[7] = (b.w - mean) * rstd * g1.w + c1.w;
    float4* ow = (float4*)(g_hln + (size_t)w * DD);
    ow[lane * 2] = make_float4(v[0], v[1], v[2], v[3]);
    ow[lane * 2 + 1] = make_float4(v[4], v[5], v[6], v[7]);
    split8_store(g_hhi + (size_t)w * DD + lane * 8,
                 g_hlo + (size_t)w * DD + lane * 8, v);

    if (PROJ) {
        float acc8[8];
#pragma unroll
        for (int t = 0; t < 8; ++t) acc8[t] = 0.f;
        int f0 = lane * 8;
#pragma unroll
        for (int j = 0; j < 8; ++j) {
            int f = f0 + j;
            float x = v[j];
            float2 wir = *(const float2*)&Wir[f * 2];
            float2 wor = *(const float2*)&Wor[f * 2];
            float2 wia = *(const float2*)&Wia[f * 2];
            float2 woa = *(const float2*)&Woa[f * 2];
            acc8[0] += x * wir.x; acc8[1] += x * wir.y;
            acc8[2] += x * wor.x; acc8[3] += x * wor.y;
            acc8[4] += x * wia.x; acc8[5] += x * wia.y;
            acc8[6] += x * woa.x; acc8[7] += x * woa.y;
        }
#pragma unroll
        for (int o = 16; o; o >>= 1)
#pragma unroll
            for (int t = 0; t < 8; ++t)
                acc8[t] += __shfl_xor_sync(0xffffffffu, acc8[t], o);
        if (lane == 0) {
            *(float4*)&g_r4[w * 4] = make_float4(acc8[0], acc8[1], acc8[2], acc8[3]);
            *(float4*)&g_z4[w * 4] = make_float4(acc8[4], acc8[5], acc8[6], acc8[7]);
        }
    }
}

// ---------------- gates (+ warp-aggregated compaction) ------------------------
// forward-exact reduction of hard gumbel-softmax: gate = argmax(logits+g);
// per-node temperature is argmax-invariant; straight-through == hard fwd.
__global__ void k_gates(const float* __restrict__ bi, const float* __restrict__ bo,
                        const float* __restrict__ gum) {
    int i = blockIdx.x * blockDim.x + threadIdx.x;
    bool valid = (i < NN);
    int gi = 0;
    if (valid) {
        float4 rr = *(const float4*)&g_r4[i * 4];
        float sx = 0.f, sy = 0.f, sz = 0.f, sw = 0.f;
        int beg = g_rowptr[i], end = g_rowptr[i + 1];
        for (int p = beg; p < end; ++p) {
            int v = g_col[p];
            float4 z = *(const float4*)&g_z4[v * 4];
            sx += z.x; sy += z.y; sz += z.z; sw += z.w;
        }
        float in0 = rr.x + sx + bi[0] + gum[i * 2 + 0];
        float in1 = rr.y + sy + bi[1] + gum[i * 2 + 1];
        float ot0 = rr.z + sz + bo[0] + gum[2 * NN + i * 2 + 0];
        float ot1 = rr.w + sw + bo[1] + gum[2 * NN + i * 2 + 1];
        gi = (in0 >= in1) ? 1 : 0;
        g_gin[i] = (unsigned char)gi;
        g_gout[i] = (ot0 >= ot1) ? 1 : 0;
    }
    unsigned m = __ballot_sync(0xffffffffu, valid && gi);
    if (m) {
        int lane = threadIdx.x & 31;
        int leader = __ffs(m) - 1;
        int base = 0;
        if (lane == leader) base = atomicAdd(&g_nact, __popc(m));
        base = __shfl_sync(0xffffffffu, base, leader);
        if (valid && gi)
            g_list[base + __popc(m & ((1u << lane) - 1))] = i;
    }
}

// ---------------- compacted gated aggregation (warp per active node) ---------
__global__ void k_agg_c() {
    int j = (blockIdx.x * blockDim.x + threadIdx.x) >> 5;
    int lane = threadIdx.x & 31;
    if (j >= g_nact) return;
    int node = g_list[j];
    float av[8] = {0.f, 0.f, 0.f, 0.f, 0.f, 0.f, 0.f, 0.f};
    int beg = g_rowptr[node], end = g_rowptr[node + 1];
    for (int p = beg; p < end; ++p) {
        int v = g_col[p];
        if (!g_gout[v]) continue;
        const float4* r = (const float4*)(g_hln + (size_t)v * DD);
        float4 x0 = r[lane * 2], x1 = r[lane * 2 + 1];
        av[0] += x0.x; av[1] += x0.y; av[2] += x0.z; av[3] += x0.w;
        av[4] += x1.x; av[5] += x1.y; av[6] += x1.z; av[7] += x1.w;
    }
    split8_store(g_ahi + (size_t)j * DD + lane * 8,
                 g_alo + (size_t)j * DD + lane * 8, av);
}

// ---------------- mma.sync fp16-split GEMM (plane inputs) ---------------------
// EPI: 0 = relu (enc), 1 = none (dec), 2 = root (relu only where gin==0),
//      3 = compact agg (M=g_nact, C row = g_list[r], rmw add + relu, no bias)
// smem per buffer (half2): AH[r*18+w] w=0..7 (interleaved word order
// w = t*2 + kh, word = halves {k=kh*8+2t, +1}); AL at +2304; BH at 4608 + n*10+w;
// BL at +640.
template <int EPI>
__global__ __launch_bounds__(256, 2) void k_mma(
    const __half* __restrict__ Ahi, const __half* __restrict__ Alo, int K,
    const __half2* __restrict__ Bhi, const __half2* __restrict__ Blo,
    const float* __restrict__ bias, float* __restrict__ C, int Mparam, int Nc) {
    __shared__ __half2 sm[11776];
    const int M = (EPI == 3) ? g_nact : Mparam;
    const int rowBase = blockIdx.y * 128;
    if (rowBase >= M) return;
    const int tid = threadIdx.x;
    const int warp = tid >> 5, lane = tid & 31;
    const int gid = lane >> 2, tig = lane & 3;
    const int wm = warp >> 1, wn = warp & 1;
    const int cb = blockIdx.x, colBase = cb * 64;
    const int nT = K >> 4;

    float acc[2][4][4];
#pragma unroll
    for (int i = 0; i < 2; ++i)
#pragma unroll
        for (int j = 0; j < 4; ++j)
#pragma unroll
            for (int q = 0; q < 4; ++q) acc[i][j][q] = 0.f;

    const int aR = tid & 127, aKh = tid >> 7;  // A: row, k-octet
    const int bN = tid & 63, bQ = tid >> 6;    // B: col, k-quad

    auto gload = [&](int t, uint4& ah, uint4& al, uint2& bh, uint2& bl) {
        int kt = t << 4;
        int r0 = rowBase + aR;
        if (r0 < M) {
            size_t ao = (size_t)r0 * K + kt + aKh * 8;
            ah = *(const uint4*)(Ahi + ao);
            al = *(const uint4*)(Alo + ao);
        } else {
            ah = make_uint4(0, 0, 0, 0);
            al = ah;
        }
        size_t bo = ((size_t)(cb * nT + t) * 64 + bN) * 8 + bQ * 2;
        bh = *(const uint2*)&Bhi[bo];
        bl = *(const uint2*)&Blo[bo];
    };

    auto sts = [&](int buf, const uint4& ah, const uint4& al,
                   const uint2& bh, const uint2& bl) {
        __half2* S = sm + buf * 5888;
        int ai = aR * 18 + aKh;  // word w = t*2 + aKh
        ((uint32_t*)S)[ai + 0] = ah.x;
        ((uint32_t*)S)[ai + 2] = ah.y;
        ((uint32_t*)S)[ai + 4] = ah.z;
        ((uint32_t*)S)[ai + 6] = ah.w;
        ((uint32_t*)S)[2304 + ai + 0] = al.x;
        ((uint32_t*)S)[2304 + ai + 2] = al.y;
        ((uint32_t*)S)[2304 + ai + 4] = al.z;
        ((uint32_t*)S)[2304 + ai + 6] = al.w;
        // B: pair p (k = bQ*4 + 2p) -> word w = ((bQ&1)*2+p)*2 + (bQ>>1)
        int w0 = ((bQ & 1) * 2) * 2 + (bQ >> 1);
        int bi = 4608 + bN * 10;
        ((uint32_t*)S)[bi + w0] = bh.x;
        ((uint32_t*)S)[bi + w0 + 2] = bh.y;
        ((uint32_t*)S)[640 + bi + w0] = bl.x;
        ((uint32_t*)S)[640 + bi + w0 + 2] = bl.y;
    };

    auto compute = [&](int buf) {
        const __half2* S = sm + buf * 5888;
        uint2 ah[2][2], al[2][2], bh[4], bl[4];
#pragma unroll
        for (int mt = 0; mt < 2; ++mt) {
            int r0 = (wm * 32 + mt * 16 + gid) * 18 + tig * 2;
            ah[mt][0] = *(const uint2*)&S[r0];
            ah[mt][1] = *(const uint2*)&S[r0 + 8 * 18];
            al[mt][0] = *(const uint2*)&S[2304 + r0];
            al[mt][1] = *(const uint2*)&S[2304 + r0 + 8 * 18];
        }
#pragma unroll
        for (int nt = 0; nt < 4; ++nt) {
            int n0 = 4608 + (wn * 32 + nt * 8 + gid) * 10 + tig * 2;
            bh[nt] = *(const uint2*)&S[n0];
            bl[nt] = *(const uint2*)&S[640 + n0];
        }
#pragma unroll
        for (int mt = 0; mt < 2; ++mt)
#pragma unroll
            for (int nt = 0; nt < 4; ++nt) {
                float* c = acc[mt][nt];
                mma16816(c, ah[mt][0].x, ah[mt][1].x, ah[mt][0].y, ah[mt][1].y,
                         bh[nt].x, bh[nt].y);
                mma16816(c, al[mt][0].x, al[mt][1].x, al[mt][0].y, al[mt][1].y,
                         bh[nt].x, bh[nt].y);
                mma16816(c, ah[mt][0].x, ah[mt][1].x, ah[mt][0].y, ah[mt][1].y,
                         bl[nt].x, bl[nt].y);
            }
    };

    uint4 cah, cal;
    uint2 cbh, cbl;
    gload(0, cah, cal, cbh, cbl);
    sts(0, cah, cal, cbh, cbl);
    __syncthreads();
    for (int t = 0; t < nT; ++t) {
        uint4 nah, nal;
        uint2 nbh, nbl;
        bool more = (t + 1 < nT);
        if (more) gload(t + 1, nah, nal, nbh, nbl);
        compute(t & 1);
        if (more) sts((t + 1) & 1, nah, nal, nbh, nbl);
        __syncthreads();
    }

#pragma unroll
    for (int mt = 0; mt < 2; ++mt) {
        int rr = rowBase + wm * 32 + mt * 16 + gid;
#pragma unroll
        for (int nt = 0; nt < 4; ++nt) {
            int col = colBase + wn * 32 + nt * 8 + tig * 2;
            float* a = acc[mt][nt];
#pragma unroll
            for (int h = 0; h < 2; ++h) {
                int r = rr + h * 8;
                if (r >= M) continue;
                float2 o = make_float2(a[h * 2 + 0], a[h * 2 + 1]);
                if (EPI != 3) {
                    float2 bv = *(const float2*)(bias + col);
                    o.x += bv.x;
                    o.y += bv.y;
                }
                if (EPI == 0) {
                    o.x = fmaxf(o.x, 0.f);
                    o.y = fmaxf(o.y, 0.f);
                    *(float2*)(C + (size_t)r * Nc + col) = o;
                } else if (EPI == 1) {
                    *(float2*)(C + (size_t)r * Nc + col) = o;
                } else if (EPI == 2) {
                    if (!g_gin[r]) {
                        o.x = fmaxf(o.x, 0.f);
                        o.y = fmaxf(o.y, 0.f);
                    }
                    *(float2*)(C + (size_t)r * Nc + col) = o;
                } else {
                    int node = g_list[r];
                    float2 old = *(const float2*)(C + (size_t)node * Nc + col);
                    o.x = fmaxf(old.x + o.x, 0.f);
                    o.y = fmaxf(old.y + o.y, 0.f);
                    *(float2*)(C + (size_t)node * Nc + col) = o;
                }
            }
        }
    }
}

// ---------------- launch -----------------------------------------------------
extern "C" void kernel_launch(void* const* d_in, const int* in_sizes, int n_in,
                              void* d_out, int out_size) {
    const float* x = (const float*)d_in[0];
    const int* ei = (const int*)d_in[1];
    const float* gum = (const float*)d_in[2];
    const float* W_enc = (const float*)d_in[3];
    const float* b_enc = (const float*)d_in[4];
    const float* W_root = (const float*)d_in[5];
    const float* W_agg = (const float*)d_in[6];
    const float* b_env = (const float*)d_in[7];
    const float* Wir = (const float*)d_in[8];
    const float* Wia = (const float*)d_in[9];
    const float* bi = (const float*)d_in[10];
    const float* Wor = (const float*)d_in[11];
    const float* Woa = (const float*)d_in[12];
    const float* bo = (const float*)d_in[13];
    // d_in[14..16] = temperature net: forward-dead (argmax is temp-invariant)
    const float* ln_g = (const float*)d_in[17];
    const float* ln_b = (const float*)d_in[18];
    const float* W_dec = (const float*)d_in[19];
    const float* b_dec = (const float*)d_in[20];
    float* out = (float*)d_out;

    float* ph;
    __half *xhi, *xlo, *hhi, *hlo, *ahi, *alo;
    __half2 *whi, *wlo;
    cudaGetSymbolAddress((void**)&ph, g_h);
    cudaGetSymbolAddress((void**)&xhi, g_xhi);
    cudaGetSymbolAddress((void**)&xlo, g_xlo);
    cudaGetSymbolAddress((void**)&hhi, g_hhi);
    cudaGetSymbolAddress((void**)&hlo, g_hlo);
    cudaGetSymbolAddress((void**)&ahi, g_ahi);
    cudaGetSymbolAddress((void**)&alo, g_alo);
    cudaGetSymbolAddress((void**)&whi, g_whi);
    cudaGetSymbolAddress((void**)&wlo, g_wlo);

    int wgrid = (NN * 32 + 255) / 256;
    int ngrid = (NN + 255) / 256;
    dim3 gMain(DD / 64, (NN + 127) / 128);   // 4 x 391
    dim3 gDec(DOUT / 64, (NN + 127) / 128);  // 1 x 391

    // CSR build (edge_index is a fresh input each call)
    k_zero_cnt<<<ngrid, 256>>>();
    k_hist<<<(EE + 255) / 256, 256>>>(ei);
    k_scan<<<1, 1024>>>();
    k_scatter<<<(EE + 255) / 256, 256>>>(ei);

    // pack weights + x into fp16 split images/planes
    k_pack_w<<<(DIN * DD / 2 + 255) / 256, 256>>>(W_enc, DIN, DD, IMG_ENC);
    for (int l = 0; l < 3; ++l) {
        k_pack_w<<<(DD * DD / 2 + 255) / 256, 256>>>(
            W_root + (size_t)l * DD * DD, DD, DD, IMG_ROOT(l));
        k_pack_w<<<(DD * DD / 2 + 255) / 256, 256>>>(
            W_agg + (size_t)l * DD * DD, DD, DD, IMG_AGG(l));
    }
    k_pack_w<<<(DD * DOUT / 2 + 255) / 256, 256>>>(W_dec, DD, DOUT, IMG_DEC);
    k_pack_x<<<(NN * DIN / 8 + 255) / 256, 256>>>(x);

    // encoder: h = relu(x @ W_enc + b_enc)
    k_mma<0><<<gMain, 256>>>(xhi, xlo, DIN, whi + IMG_ENC, wlo + IMG_ENC,
                             b_enc, ph, NN, DD);

    for (int l = 0; l < 3; ++l) {
        k_ln<true><<<wgrid, 256>>>(ph, ln_g, ln_b, Wir, Wia, Wor, Woa);
        k_gates<<<ngrid, 256>>>(bi, bo, gum + (size_t)l * 2 * NN * 2);
        k_agg_c<<<wgrid, 256>>>();
        // root (dense; relu deferred for gin rows)
        k_mma<2><<<gMain, 256>>>(hhi, hlo, DD, whi + IMG_ROOT(l),
                                 wlo + IMG_ROOT(l), b_env + (size_t)l * DD,
                                 ph, NN, DD);
        // agg (compacted; add + relu)
        k_mma<3><<<gMain, 256>>>(ahi, alo, DD, whi + IMG_AGG(l),
                                 wlo + IMG_AGG(l), nullptr, ph, 0, DD);
    }

    k_ln<false><<<wgrid, 256>>>(ph, ln_g, ln_b, nullptr, nullptr, nullptr, nullptr);
    k_mma<1><<<gDec, 256>>>(hhi, hlo, DD, whi + IMG_DEC, wlo + IMG_DEC,
                            b_dec, out, NN, DOUT);
}

// round 13
// speedup vs baseline: 2.0071x; 1.3365x over previous
#include <cuda_runtime.h>
#include <cuda_fp16.h>
#include <cstdint>

#define NN   50000
#define EE   800000
#define DIN  128
#define DD   256
#define DOUT 64

// ---------------- scratch (device globals) ----------------------------------
__device__ __align__(16) float g_h[NN * DD];
__device__ __align__(16) float g_hln[NN * DD];
__device__ __align__(16) float g_r4[NN * 4];
__device__ __align__(16) float g_z4[NN * 4];
// fp16 split planes, stored as uint32 (half2) words in the GEMM smem image
// layout: per row, per 16-k tile, 8 words; word w = 2t + kh holds halves
// {k = kt*16 + kh*8 + 2t, k+1}.
__device__ __align__(16) uint32_t g_xhi[NN * DIN / 2];
__device__ __align__(16) uint32_t g_xlo[NN * DIN / 2];
__device__ __align__(16) uint32_t g_hhi[NN * DD / 2];
__device__ __align__(16) uint32_t g_hlo[NN * DD / 2];
__device__ __align__(16) uint32_t g_ahi[NN * DD / 2];  // compacted agg rows
__device__ __align__(16) uint32_t g_alo[NN * DD / 2];
// W images: [cb][kt][n(64)][8 words], same word interleave, B[n][k]=W[k][n]
#define IMG_ENC 0
#define IMG_ROOT(l) (16384 + (l) * 32768)
#define IMG_AGG(l)  (114688 + (l) * 32768)
#define IMG_DEC 212992
#define IMG_TOT 221184
__device__ __align__(16) uint32_t g_whi[IMG_TOT];
__device__ __align__(16) uint32_t g_wlo[IMG_TOT];
// CSR + gates
__device__ int g_rowptr[NN + 1];
__device__ int g_cnt[NN];
__device__ int g_fill[NN];
__device__ int g_col[EE];
__device__ unsigned char g_gin[NN];
__device__ unsigned char g_gout[NN];
__device__ int g_nact;
__device__ int g_list[NN];

// ---------------- helpers -----------------------------------------------------
__device__ __forceinline__ uint32_t pack_h2(float a, float b, float& ra, float& rb) {
    __half ha = __float2half_rn(a), hb = __float2half_rn(b);
    ra = a - __half2float(ha);
    rb = b - __half2float(hb);
    __half2 h = __halves2half2(ha, hb);
    return *(uint32_t*)&h;
}
__device__ __forceinline__ uint32_t pack_h2r(float a, float b) {
    __half2 h = __halves2half2(__float2half_rn(a), __float2half_rn(b));
    return *(uint32_t*)&h;
}
// 8 consecutive k-values of one row -> 4 hi + 4 lo words at stride 2
__device__ __forceinline__ void split8_scatter(uint32_t* hp, uint32_t* lp,
                                               const float* v) {
#pragma unroll
    for (int t = 0; t < 4; ++t) {
        float ra, rb;
        hp[t * 2] = pack_h2(v[2 * t], v[2 * t + 1], ra, rb);
        lp[t * 2] = pack_h2r(ra, rb);
    }
}

__device__ __forceinline__ void mma16816(float* c, uint32_t a0, uint32_t a1,
                                         uint32_t a2, uint32_t a3,
                                         uint32_t b0, uint32_t b1) {
    asm volatile(
        "mma.sync.aligned.m16n8k16.row.col.f32.f16.f16.f32 "
        "{%0,%1,%2,%3}, {%4,%5,%6,%7}, {%8,%9}, {%0,%1,%2,%3};"
        : "+f"(c[0]), "+f"(c[1]), "+f"(c[2]), "+f"(c[3])
        : "r"(a0), "r"(a1), "r"(a2), "r"(a3), "r"(b0), "r"(b1));
}

__device__ __forceinline__ uint32_t smem_u32(const void* p) {
    uint32_t a;
    asm("{ .reg .u64 t; cvta.to.shared.u64 t, %1; cvt.u32.u64 %0, t; }"
        : "=r"(a) : "l"(p));
    return a;
}
__device__ __forceinline__ void cp16(uint32_t dst, const void* src, int sz) {
    asm volatile("cp.async.cg.shared.global [%0], [%1], 16, %2;"
                 :: "r"(dst), "l"(src), "r"(sz) : "memory");
}
__device__ __forceinline__ void cp_commit() {
    asm volatile("cp.async.commit_group;" ::: "memory");
}
__device__ __forceinline__ void cp_wait2() {
    asm volatile("cp.async.wait_group 2;" ::: "memory");
}

// ---------------- CSR build --------------------------------------------------
__global__ void k_zero_cnt() {
    int i = blockIdx.x * blockDim.x + threadIdx.x;
    if (i < NN) g_cnt[i] = 0;
}
__global__ void k_hist(const int* __restrict__ ei) {
    int e = blockIdx.x * blockDim.x + threadIdx.x;
    if (e < EE) atomicAdd(&g_cnt[ei[e]], 1);
}
__global__ void k_scan() {
    __shared__ int sh[1024];
    int t = threadIdx.x;
    const int CH = (NN + 1023) / 1024;
    int s0 = t * CH;
    int s = 0;
    for (int i = 0; i < CH; ++i) {
        int idx = s0 + i;
        if (idx < NN) s += g_cnt[idx];
    }
    sh[t] = s;
    __syncthreads();
    for (int off = 1; off < 1024; off <<= 1) {
        int tmp = (t >= off) ? sh[t - off] : 0;
        __syncthreads();
        sh[t] += tmp;
        __syncthreads();
    }
    int run = sh[t] - s;
    for (int i = 0; i < CH; ++i) {
        int idx = s0 + i;
        if (idx < NN) {
            g_rowptr[idx] = run;
            run += g_cnt[idx];
            g_fill[idx] = 0;
        }
    }
    if (t == 0) g_rowptr[NN] = EE;
}
__global__ void k_scatter(const int* __restrict__ ei) {
    int e = blockIdx.x * blockDim.x + threadIdx.x;
    if (e < EE) {
        int u = ei[e];
        int v = ei[EE + e];
        int pos = g_rowptr[u] + atomicAdd(&g_fill[u], 1);
        g_col[pos] = v;
    }
}

// ---------------- packing ------------------------------------------------------
__global__ void k_pack_x(const float* __restrict__ x) {
    int i = blockIdx.x * blockDim.x + threadIdx.x;  // octet index
    if (i >= NN * DIN / 8) return;
    int r = i >> 4, oct = i & 15;
    int kt = oct >> 1, kh = oct & 1;
    const float4* p = (const float4*)(x + (size_t)r * DIN + oct * 8);
    float4 a = p[0], b = p[1];
    float v[8] = {a.x, a.y, a.z, a.w, b.x, b.y, b.z, b.w};
    uint32_t base = (uint32_t)r * (DIN / 2) + kt * 8 + kh;
    split8_scatter(g_xhi + base, g_xlo + base, v);
}

// all weight images in one kernel
__global__ void k_pack_w(const float* __restrict__ Wenc,
                         const float* __restrict__ Wroot,
                         const float* __restrict__ Wagg,
                         const float* __restrict__ Wdec) {
    int i = blockIdx.x * blockDim.x + threadIdx.x;
    if (i >= IMG_TOT) return;
    const float* W;
    int li, K, N;
    if (i < 16384) { W = Wenc; li = i; K = DIN; N = DD; }
    else if (i < 114688) {
        int j = i - 16384;
        W = Wroot + (size_t)(j / 32768) * DD * DD;
        li = j % 32768; K = DD; N = DD;
    } else if (i < 212992) {
        int j = i - 114688;
        W = Wagg + (size_t)(j / 32768) * DD * DD;
        li = j % 32768; K = DD; N = DD;
    } else { W = Wdec; li = i - 212992; K = DD; N = DOUT; }
    int w = li & 7, n = (li >> 3) & 63, rest = li >> 9;
    int nKt = K >> 4;
    int kt = rest % nKt, cb = rest / nKt;
    int t = w >> 1, kh = w & 1;
    int k0 = kt * 16 + kh * 8 + 2 * t;
    int ng = cb * 64 + n;
    float v0 = W[(size_t)k0 * N + ng];
    float v1 = W[(size_t)(k0 + 1) * N + ng];
    float ra, rb;
    g_whi[i] = pack_h2(v0, v1, ra, rb);
    g_wlo[i] = pack_h2r(ra, rb);
}

// ---------------- LayerNorm (+ proj, + plane writes) --------------------------
template <bool PROJ>
__global__ void k_ln(const float* __restrict__ in,
                     const float* __restrict__ gam, const float* __restrict__ bet,
                     const float* __restrict__ Wir, const float* __restrict__ Wia,
                     const float* __restrict__ Wor, const float* __restrict__ Woa) {
    if (PROJ && blockIdx.x == 0 && threadIdx.x == 0) g_nact = 0;
    int w = (blockIdx.x * blockDim.x + threadIdx.x) >> 5;
    int lane = threadIdx.x & 31;
    if (w >= NN) return;
    const float4* r = (const float4*)(in + (size_t)w * DD);
    float4 a = r[lane * 2], b = r[lane * 2 + 1];
    float s = a.x + a.y + a.z + a.w + b.x + b.y + b.z + b.w;
#pragma unroll
    for (int o = 16; o; o >>= 1) s += __shfl_xor_sync(0xffffffffu, s, o);
    float mean = s * (1.0f / DD);
    float d, sq = 0.f;
    d = a.x - mean; sq += d * d; d = a.y - mean; sq += d * d;
    d = a.z - mean; sq += d * d; d = a.w - mean; sq += d * d;
    d = b.x - mean; sq += d * d; d = b.y - mean; sq += d * d;
    d = b.z - mean; sq += d * d; d = b.w - mean; sq += d * d;
#pragma unroll
    for (int o = 16; o; o >>= 1) sq += __shfl_xor_sync(0xffffffffu, sq, o);
    float rstd = rsqrtf(sq * (1.0f / DD) + 1e-5f);
    const float4* g4 = (const float4*)gam;
    const float4* b4 = (const float4*)bet;
    float4 g0 = g4[lane * 2], g1 = g4[lane * 2 + 1];
    float4 c0 = b4[lane * 2], c1 = b4[lane * 2 + 1];
    float v[8];
    v[0] = (a.x - mean) * rstd * g0.x + c0.x;
    v[1] = (a.y - mean) * rstd * g0.y + c0.y;
    v[2] = (a.z - mean) * rstd * g0.z + c0.z;
    v[3] = (a.w - mean) * rstd * g0.w + c0.w;
    v[4] = (b.x - mean) * rstd * g1.x + c1.x;
    v[5] = (b.y - mean) * rstd * g1.y + c1.y;
    v[6] = (b.z - mean) * rstd * g1.z + c1.z;
    v[7] = (b.w - mean) * rstd * g1.w + c1.w;
    float4* ow = (float4*)(g_hln + (size_t)w * DD);
    ow[lane * 2] = make_float4(v[0], v[1], v[2], v[3]);
    ow[lane * 2 + 1] = make_float4(v[4], v[5], v[6], v[7]);
    {
        uint32_t base = (uint32_t)w * (DD / 2) + (lane >> 1) * 8 + (lane & 1);
        split8_scatter(g_hhi + base, g_hlo + base, v);
    }

    if (PROJ) {
        float acc8[8];
#pragma unroll
        for (int t = 0; t < 8; ++t) acc8[t] = 0.f;
        int f0 = lane * 8;
#pragma unroll
        for (int j = 0; j < 8; ++j) {
            int f = f0 + j;
            float x = v[j];
            float2 wir = *(const float2*)&Wir[f * 2];
            float2 wor = *(const float2*)&Wor[f * 2];
            float2 wia = *(const float2*)&Wia[f * 2];
            float2 woa = *(const float2*)&Woa[f * 2];
            acc8[0] += x * wir.x; acc8[1] += x * wir.y;
            acc8[2] += x * wor.x; acc8[3] += x * wor.y;
            acc8[4] += x * wia.x; acc8[5] += x * wia.y;
            acc8[6] += x * woa.x; acc8[7] += x * woa.y;
        }
#pragma unroll
        for (int o = 16; o; o >>= 1)
#pragma unroll
            for (int t = 0; t < 8; ++t)
                acc8[t] += __shfl_xor_sync(0xffffffffu, acc8[t], o);
        if (lane == 0) {
            *(float4*)&g_r4[w * 4] = make_float4(acc8[0], acc8[1], acc8[2], acc8[3]);
            *(float4*)&g_z4[w * 4] = make_float4(acc8[4], acc8[5], acc8[6], acc8[7]);
        }
    }
}

// ---------------- gates (+ warp-aggregated compaction) ------------------------
// forward-exact reduction of hard gumbel-softmax: gate = argmax(logits+g);
// per-node temperature is argmax-invariant; straight-through == hard fwd.
__global__ void k_gates(const float* __restrict__ bi, const float* __restrict__ bo,
                        const float* __restrict__ gum) {
    int i = blockIdx.x * blockDim.x + threadIdx.x;
    bool valid = (i < NN);
    int gi = 0;
    if (valid) {
        float4 rr = *(const float4*)&g_r4[i * 4];
        float sx = 0.f, sy = 0.f, sz = 0.f, sw = 0.f;
        int beg = g_rowptr[i], end = g_rowptr[i + 1];
        for (int p = beg; p < end; ++p) {
            int v = g_col[p];
            float4 z = *(const float4*)&g_z4[v * 4];
            sx += z.x; sy += z.y; sz += z.z; sw += z.w;
        }
        float in0 = rr.x + sx + bi[0] + gum[i * 2 + 0];
        float in1 = rr.y + sy + bi[1] + gum[i * 2 + 1];
        float ot0 = rr.z + sz + bo[0] + gum[2 * NN + i * 2 + 0];
        float ot1 = rr.w + sw + bo[1] + gum[2 * NN + i * 2 + 1];
        gi = (in0 >= in1) ? 1 : 0;
        g_gin[i] = (unsigned char)gi;
        g_gout[i] = (ot0 >= ot1) ? 1 : 0;
    }
    unsigned m = __ballot_sync(0xffffffffu, valid && gi);
    if (m) {
        int lane = threadIdx.x & 31;
        int leader = __ffs(m) - 1;
        int base = 0;
        if (lane == leader) base = atomicAdd(&g_nact, __popc(m));
        base = __shfl_sync(0xffffffffu, base, leader);
        if (valid && gi)
            g_list[base + __popc(m & ((1u << lane) - 1))] = i;
    }
}

// ---------------- compacted gated aggregation (warp per active node) ---------
__global__ void k_agg_c() {
    int j = (blockIdx.x * blockDim.x + threadIdx.x) >> 5;
    int lane = threadIdx.x & 31;
    if (j >= g_nact) return;
    int node = g_list[j];
    float av[8] = {0.f, 0.f, 0.f, 0.f, 0.f, 0.f, 0.f, 0.f};
    int beg = g_rowptr[node], end = g_rowptr[node + 1];
    for (int p = beg; p < end; ++p) {
        int v = g_col[p];
        if (!g_gout[v]) continue;
        const float4* r = (const float4*)(g_hln + (size_t)v * DD);
        float4 x0 = r[lane * 2], x1 = r[lane * 2 + 1];
        av[0] += x0.x; av[1] += x0.y; av[2] += x0.z; av[3] += x0.w;
        av[4] += x1.x; av[5] += x1.y; av[6] += x1.z; av[7] += x1.w;
    }
    uint32_t base = (uint32_t)j * (DD / 2) + (lane >> 1) * 8 + (lane & 1);
    split8_scatter(g_ahi + base, g_alo + base, av);
}

// ---------------- cp.async fp16-split GEMM ------------------------------------
// EPI: 0 = relu (enc), 1 = none (dec), 2 = root (relu only where gin==0),
//      3 = compact agg (M=g_nact, C row = g_list[r], rmw add + relu, no bias)
// 4-stage cp.async pipeline; stage = 3072 words: Ahi[0,1024) Alo[1024,2048)
// Bhi[2048,2560) Blo[2560,3072). A word idx in stage: r*8 + w; B: n*8 + w.
template <int EPI>
__global__ __launch_bounds__(256, 2) void k_mma(
    const uint32_t* __restrict__ Ahi, const uint32_t* __restrict__ Alo, int K,
    const uint32_t* __restrict__ Bhi, const uint32_t* __restrict__ Blo,
    const float* __restrict__ bias, float* __restrict__ C, int Mparam, int Nc) {
    __shared__ __align__(16) uint32_t sm[12288];  // 4 stages x 3072
    const int M = (EPI == 3) ? g_nact : Mparam;
    const int rowBase = blockIdx.y * 128;
    if (rowBase >= M) return;
    const int tid = threadIdx.x;
    const int warp = tid >> 5, lane = tid & 31;
    const int gid = lane >> 2, tig = lane & 3;
    const int wm = warp >> 1, wn = warp & 1;
    const int cb = blockIdx.x, colBase = cb * 64;
    const int nT = K >> 4;
    const int Kw = K >> 1;  // words per A row

    float acc[2][4][4];
#pragma unroll
    for (int i = 0; i < 2; ++i)
#pragma unroll
        for (int j = 0; j < 4; ++j)
#pragma unroll
            for (int q = 0; q < 4; ++q) acc[i][j][q] = 0.f;

    // cp.async roles
    const int aR = tid >> 1, hf = tid & 1;
    const int r0 = rowBase + aR;
    const int rc = (r0 < M) ? r0 : (M - 1);
    const uint32_t* gAh = Ahi + (size_t)rc * Kw + hf * 4;
    const uint32_t* gAl = Alo + (size_t)rc * Kw + hf * 4;
    const int szA = (r0 < M) ? 16 : 0;
    const int bc = tid & 127;
    const bool blo = (tid >= 128);
    const uint32_t* gB = (blo ? Blo : Bhi) + (size_t)cb * nT * 512 + bc * 4;
    const uint32_t smb = smem_u32(sm);
    const uint32_t dA0 = smb + (aR * 8 + hf * 4) * 4;
    const uint32_t dA1 = dA0 + 4096;
    const uint32_t dB = smb + (2048 + (blo ? 512 : 0) + bc * 4) * 4;

    auto issue = [&](int t) {
        uint32_t off = (uint32_t)(t & 3) * 12288;
        cp16(dA0 + off, gAh + (size_t)t * 8, szA);
        cp16(dA1 + off, gAl + (size_t)t * 8, szA);
        cp16(dB + off, gB + (size_t)t * 512, 16);
        cp_commit();
    };

    issue(0);
    if (nT > 1) issue(1);
    if (nT > 2) issue(2);

    for (int t = 0; t < nT; ++t) {
        cp_wait2();
        __syncthreads();
        if (t + 3 < nT) issue(t + 3);
        const uint32_t* S = sm + (t & 3) * 3072;
        uint2 ah[2][2], al[2][2], bh[4], bl[4];
#pragma unroll
        for (int mt = 0; mt < 2; ++mt) {
            int r = wm * 32 + mt * 16 + gid;
            ah[mt][0] = *(const uint2*)&S[r * 8 + tig * 2];
            ah[mt][1] = *(const uint2*)&S[(r + 8) * 8 + tig * 2];
            al[mt][0] = *(const uint2*)&S[1024 + r * 8 + tig * 2];
            al[mt][1] = *(const uint2*)&S[1024 + (r + 8) * 8 + tig * 2];
        }
#pragma unroll
        for (int nt = 0; nt < 4; ++nt) {
            int n = wn * 32 + nt * 8 + gid;
            bh[nt] = *(const uint2*)&S[2048 + n * 8 + tig * 2];
            bl[nt] = *(const uint2*)&S[2560 + n * 8 + tig * 2];
        }
        // 3 passes of 8 independent MMAs (break RAW chains per accumulator)
#pragma unroll
        for (int mt = 0; mt < 2; ++mt)
#pragma unroll
            for (int nt = 0; nt < 4; ++nt)
                mma16816(acc[mt][nt], ah[mt][0].x, ah[mt][1].x, ah[mt][0].y,
                         ah[mt][1].y, bh[nt].x, bh[nt].y);
#pragma unroll
        for (int mt = 0; mt < 2; ++mt)
#pragma unroll
            for (int nt = 0; nt < 4; ++nt)
                mma16816(acc[mt][nt], al[mt][0].x, al[mt][1].x, al[mt][0].y,
                         al[mt][1].y, bh[nt].x, bh[nt].y);
#pragma unroll
        for (int mt = 0; mt < 2; ++mt)
#pragma unroll
            for (int nt = 0; nt < 4; ++nt)
                mma16816(acc[mt][nt], ah[mt][0].x, ah[mt][1].x, ah[mt][0].y,
                         ah[mt][1].y, bl[nt].x, bl[nt].y);
        __syncthreads();
    }

#pragma unroll
    for (int mt = 0; mt < 2; ++mt) {
        int rr = rowBase + wm * 32 + mt * 16 + gid;
#pragma unroll
        for (int nt = 0; nt < 4; ++nt) {
            int col = colBase + wn * 32 + nt * 8 + tig * 2;
            float* a = acc[mt][nt];
#pragma unroll
            for (int h = 0; h < 2; ++h) {
                int r = rr + h * 8;
                if (r >= M) continue;
                float2 o = make_float2(a[h * 2 + 0], a[h * 2 + 1]);
                if (EPI != 3) {
                    float2 bv = *(const float2*)(bias + col);
                    o.x += bv.x;
                    o.y += bv.y;
                }
                if (EPI == 0) {
                    o.x = fmaxf(o.x, 0.f);
                    o.y = fmaxf(o.y, 0.f);
                    *(float2*)(C + (size_t)r * Nc + col) = o;
                } else if (EPI == 1) {
                    *(float2*)(C + (size_t)r * Nc + col) = o;
                } else if (EPI == 2) {
                    if (!g_gin[r]) {
                        o.x = fmaxf(o.x, 0.f);
                        o.y = fmaxf(o.y, 0.f);
                    }
                    *(float2*)(C + (size_t)r * Nc + col) = o;
                } else {
                    int node = g_list[r];
                    float2 old = *(const float2*)(C + (size_t)node * Nc + col);
                    o.x = fmaxf(old.x + o.x, 0.f);
                    o.y = fmaxf(old.y + o.y, 0.f);
                    *(float2*)(C + (size_t)node * Nc + col) = o;
                }
            }
        }
    }
}

// ---------------- launch -----------------------------------------------------
extern "C" void kernel_launch(void* const* d_in, const int* in_sizes, int n_in,
                              void* d_out, int out_size) {
    const float* x = (const float*)d_in[0];
    const int* ei = (const int*)d_in[1];
    const float* gum = (const float*)d_in[2];
    const float* W_enc = (const float*)d_in[3];
    const float* b_enc = (const float*)d_in[4];
    const float* W_root = (const float*)d_in[5];
    const float* W_agg = (const float*)d_in[6];
    const float* b_env = (const float*)d_in[7];
    const float* Wir = (const float*)d_in[8];
    const float* Wia = (const float*)d_in[9];
    const float* bi = (const float*)d_in[10];
    const float* Wor = (const float*)d_in[11];
    const float* Woa = (const float*)d_in[12];
    const float* bo = (const float*)d_in[13];
    // d_in[14..16] = temperature net: forward-dead (argmax is temp-invariant)
    const float* ln_g = (const float*)d_in[17];
    const float* ln_b = (const float*)d_in[18];
    const float* W_dec = (const float*)d_in[19];
    const float* b_dec = (const float*)d_in[20];
    float* out = (float*)d_out;

    float* ph;
    uint32_t *xhi, *xlo, *hhi, *hlo, *ahi, *alo, *whi, *wlo;
    cudaGetSymbolAddress((void**)&ph, g_h);
    cudaGetSymbolAddress((void**)&xhi, g_xhi);
    cudaGetSymbolAddress((void**)&xlo, g_xlo);
    cudaGetSymbolAddress((void**)&hhi, g_hhi);
    cudaGetSymbolAddress((void**)&hlo, g_hlo);
    cudaGetSymbolAddress((void**)&ahi, g_ahi);
    cudaGetSymbolAddress((void**)&alo, g_alo);
    cudaGetSymbolAddress((void**)&whi, g_whi);
    cudaGetSymbolAddress((void**)&wlo, g_wlo);

    int wgrid = (NN * 32 + 255) / 256;
    int ngrid = (NN + 255) / 256;
    dim3 gMain(DD / 64, (NN + 127) / 128);   // 4 x 391
    dim3 gDec(DOUT / 64, (NN + 127) / 128);  // 1 x 391

    // CSR build (edge_index is a fresh input each call)
    k_zero_cnt<<<ngrid, 256>>>();
    k_hist<<<(EE + 255) / 256, 256>>>(ei);
    k_scan<<<1, 1024>>>();
    k_scatter<<<(EE + 255) / 256, 256>>>(ei);

    // pack weights + x into split-plane images
    k_pack_w<<<(IMG_TOT + 255) / 256, 256>>>(W_enc, W_root, W_agg, W_dec);
    k_pack_x<<<(NN * DIN / 8 + 255) / 256, 256>>>(x);

    // encoder: h = relu(x @ W_enc + b_enc)
    k_mma<0><<<gMain, 256>>>(xhi, xlo, DIN, whi + IMG_ENC, wlo + IMG_ENC,
                             b_enc, ph, NN, DD);

    for (int l = 0; l < 3; ++l) {
        k_ln<true><<<wgrid, 256>>>(ph, ln_g, ln_b, Wir, Wia, Wor, Woa);
        k_gates<<<ngrid, 256>>>(bi, bo, gum + (size_t)l * 2 * NN * 2);
        k_agg_c<<<wgrid, 256>>>();
        // root (dense; relu deferred for gin rows)
        k_mma<2><<<gMain, 256>>>(hhi, hlo, DD, whi + IMG_ROOT(l),
                                 wlo + IMG_ROOT(l), b_env + (size_t)l * DD,
                                 ph, NN, DD);
        // agg (compacted; add + relu)
        k_mma<3><<<gMain, 256>>>(ahi, alo, DD, whi + IMG_AGG(l),
                                 wlo + IMG_AGG(l), nullptr, ph, 0, DD);
    }

    k_ln<false><<<wgrid, 256>>>(ph, ln_g, ln_b, nullptr, nullptr, nullptr, nullptr);
    k_mma<1><<<gDec, 256>>>(hhi, hlo, DD, whi + IMG_DEC, wlo + IMG_DEC,
                            b_dec, out, NN, DOUT);
}

// round 14
// speedup vs baseline: 2.0867x; 1.0397x over previous
#include <cuda_runtime.h>
#include <cuda_fp16.h>
#include <cstdint>

#define NN   50000
#define EE   800000
#define DIN  128
#define DD   256
#define DOUT 64

// ---------------- scratch (device globals) ----------------------------------
__device__ __align__(16) float g_h[NN * DD];
__device__ __align__(16) float g_tmp[NN * DD];   // compact agg GEMM output
__device__ __align__(16) float g_r4[NN * 4];
__device__ __align__(16) float g_z4[NN * 4];
// fp16 split planes, stored as uint32 (half2) words in the GEMM smem image
// layout: per row, per 16-k tile, 8 words; word w = 2t + kh holds halves
// {k = kt*16 + kh*8 + 2t, k+1}.
__device__ __align__(16) uint32_t g_xhi[NN * DIN / 2];
__device__ __align__(16) uint32_t g_xlo[NN * DIN / 2];
__device__ __align__(16) uint32_t g_hhi[NN * DD / 2];
__device__ __align__(16) uint32_t g_hlo[NN * DD / 2];
__device__ __align__(16) uint32_t g_ahi[NN * DD / 2];  // compacted agg rows
__device__ __align__(16) uint32_t g_alo[NN * DD / 2];
// W images: [cb][kt][n(64)][8 words], same word interleave, B[n][k]=W[k][n]
#define IMG_ENC 0
#define IMG_ROOT(l) (16384 + (l) * 32768)
#define IMG_AGG(l)  (114688 + (l) * 32768)
#define IMG_DEC 212992
#define IMG_TOT 221184
__device__ __align__(16) uint32_t g_whi[IMG_TOT];
__device__ __align__(16) uint32_t g_wlo[IMG_TOT];
// CSR + gates
__device__ int g_rowptr[NN + 1];
__device__ int g_cnt[NN];
__device__ int g_fill[NN];
__device__ int g_col[EE];
__device__ unsigned char g_gin[NN];
__device__ unsigned char g_gout[NN];
__device__ int g_nact;
__device__ int g_list[NN];
__device__ int g_pos[NN];   // node -> compact row (valid when gin)

// ---------------- helpers -----------------------------------------------------
__device__ __forceinline__ uint32_t pack_h2(float a, float b, float& ra, float& rb) {
    __half ha = __float2half_rn(a), hb = __float2half_rn(b);
    ra = a - __half2float(ha);
    rb = b - __half2float(hb);
    __half2 h = __halves2half2(ha, hb);
    return *(uint32_t*)&h;
}
__device__ __forceinline__ uint32_t pack_h2r(float a, float b) {
    __half2 h = __halves2half2(__float2half_rn(a), __float2half_rn(b));
    return *(uint32_t*)&h;
}
// 8 consecutive k-values of one row -> 4 hi + 4 lo words at stride 2
__device__ __forceinline__ void split8_scatter(uint32_t* hp, uint32_t* lp,
                                               const float* v) {
#pragma unroll
    for (int t = 0; t < 4; ++t) {
        float ra, rb;
        hp[t * 2] = pack_h2(v[2 * t], v[2 * t + 1], ra, rb);
        lp[t * 2] = pack_h2r(ra, rb);
    }
}

__device__ __forceinline__ void mma16816(float* c, uint32_t a0, uint32_t a1,
                                         uint32_t a2, uint32_t a3,
                                         uint32_t b0, uint32_t b1) {
    asm volatile(
        "mma.sync.aligned.m16n8k16.row.col.f32.f16.f16.f32 "
        "{%0,%1,%2,%3}, {%4,%5,%6,%7}, {%8,%9}, {%0,%1,%2,%3};"
        : "+f"(c[0]), "+f"(c[1]), "+f"(c[2]), "+f"(c[3])
        : "r"(a0), "r"(a1), "r"(a2), "r"(a3), "r"(b0), "r"(b1));
}

__device__ __forceinline__ uint32_t smem_u32(const void* p) {
    uint32_t a;
    asm("{ .reg .u64 t; cvta.to.shared.u64 t, %1; cvt.u32.u64 %0, t; }"
        : "=r"(a) : "l"(p));
    return a;
}
__device__ __forceinline__ void cp16(uint32_t dst, const void* src, int sz) {
    asm volatile("cp.async.cg.shared.global [%0], [%1], 16, %2;"
                 :: "r"(dst), "l"(src), "r"(sz) : "memory");
}
__device__ __forceinline__ void cp_commit() {
    asm volatile("cp.async.commit_group;" ::: "memory");
}
__device__ __forceinline__ void cp_wait2() {
    asm volatile("cp.async.wait_group 2;" ::: "memory");
}

// ---------------- CSR build --------------------------------------------------
__global__ void k_zero_cnt() {
    int i = blockIdx.x * blockDim.x + threadIdx.x;
    if (i < NN) g_cnt[i] = 0;
}
__global__ void k_hist(const int* __restrict__ ei) {
    int e = blockIdx.x * blockDim.x + threadIdx.x;
    if (e < EE) atomicAdd(&g_cnt[ei[e]], 1);
}
__global__ void k_scan() {
    __shared__ int sh[1024];
    int t = threadIdx.x;
    const int CH = (NN + 1023) / 1024;
    int s0 = t * CH;
    int s = 0;
    for (int i = 0; i < CH; ++i) {
        int idx = s0 + i;
        if (idx < NN) s += g_cnt[idx];
    }
    sh[t] = s;
    __syncthreads();
    for (int off = 1; off < 1024; off <<= 1) {
        int tmp = (t >= off) ? sh[t - off] : 0;
        __syncthreads();
        sh[t] += tmp;
        __syncthreads();
    }
    int run = sh[t] - s;
    for (int i = 0; i < CH; ++i) {
        int idx = s0 + i;
        if (idx < NN) {
            g_rowptr[idx] = run;
            run += g_cnt[idx];
            g_fill[idx] = 0;
        }
    }
    if (t == 0) g_rowptr[NN] = EE;
}
__global__ void k_scatter(const int* __restrict__ ei) {
    int e = blockIdx.x * blockDim.x + threadIdx.x;
    if (e < EE) {
        int u = ei[e];
        int v = ei[EE + e];
        int pos = g_rowptr[u] + atomicAdd(&g_fill[u], 1);
        g_col[pos] = v;
    }
}

// ---------------- packing ------------------------------------------------------
__global__ void k_pack_x(const float* __restrict__ x) {
    int i = blockIdx.x * blockDim.x + threadIdx.x;  // octet index
    if (i >= NN * DIN / 8) return;
    int r = i >> 4, oct = i & 15;
    int kt = oct >> 1, kh = oct & 1;
    const float4* p = (const float4*)(x + (size_t)r * DIN + oct * 8);
    float4 a = p[0], b = p[1];
    float v[8] = {a.x, a.y, a.z, a.w, b.x, b.y, b.z, b.w};
    uint32_t base = (uint32_t)r * (DIN / 2) + kt * 8 + kh;
    split8_scatter(g_xhi + base, g_xlo + base, v);
}

// all weight images in one kernel
__global__ void k_pack_w(const float* __restrict__ Wenc,
                         const float* __restrict__ Wroot,
                         const float* __restrict__ Wagg,
                         const float* __restrict__ Wdec) {
    int i = blockIdx.x * blockDim.x + threadIdx.x;
    if (i >= IMG_TOT) return;
    const float* W;
    int li, K, N;
    if (i < 16384) { W = Wenc; li = i; K = DIN; N = DD; }
    else if (i < 114688) {
        int j = i - 16384;
        W = Wroot + (size_t)(j / 32768) * DD * DD;
        li = j % 32768; K = DD; N = DD;
    } else if (i < 212992) {
        int j = i - 114688;
        W = Wagg + (size_t)(j / 32768) * DD * DD;
        li = j % 32768; K = DD; N = DD;
    } else { W = Wdec; li = i - 212992; K = DD; N = DOUT; }
    int w = li & 7, n = (li >> 3) & 63, rest = li >> 9;
    int nKt = K >> 4;
    int kt = rest % nKt, cb = rest / nKt;
    int t = w >> 1, kh = w & 1;
    int k0 = kt * 16 + kh * 8 + 2 * t;
    int ng = cb * 64 + n;
    float v0 = W[(size_t)k0 * N + ng];
    float v1 = W[(size_t)(k0 + 1) * N + ng];
    float ra, rb;
    g_whi[i] = pack_h2(v0, v1, ra, rb);
    g_wlo[i] = pack_h2r(ra, rb);
}

// ---------------- LayerNorm (+ proj, planes only) -----------------------------
template <bool PROJ>
__global__ void k_ln(const float* __restrict__ in,
                     const float* __restrict__ gam, const float* __restrict__ bet,
                     const float* __restrict__ Wir, const float* __restrict__ Wia,
                     const float* __restrict__ Wor, const float* __restrict__ Woa) {
    if (PROJ && blockIdx.x == 0 && threadIdx.x == 0) g_nact = 0;
    int w = (blockIdx.x * blockDim.x + threadIdx.x) >> 5;
    int lane = threadIdx.x & 31;
    if (w >= NN) return;
    const float4* r = (const float4*)(in + (size_t)w * DD);
    float4 a = r[lane * 2], b = r[lane * 2 + 1];
    float s = a.x + a.y + a.z + a.w + b.x + b.y + b.z + b.w;
#pragma unroll
    for (int o = 16; o; o >>= 1) s += __shfl_xor_sync(0xffffffffu, s, o);
    float mean = s * (1.0f / DD);
    float d, sq = 0.f;
    d = a.x - mean; sq += d * d; d = a.y - mean; sq += d * d;
    d = a.z - mean; sq += d * d; d = a.w - mean; sq += d * d;
    d = b.x - mean; sq += d * d; d = b.y - mean; sq += d * d;
    d = b.z - mean; sq += d * d; d = b.w - mean; sq += d * d;
#pragma unroll
    for (int o = 16; o; o >>= 1) sq += __shfl_xor_sync(0xffffffffu, sq, o);
    float rstd = rsqrtf(sq * (1.0f / DD) + 1e-5f);
    const float4* g4 = (const float4*)gam;
    const float4* b4 = (const float4*)bet;
    float4 g0 = g4[lane * 2], g1 = g4[lane * 2 + 1];
    float4 c0 = b4[lane * 2], c1 = b4[lane * 2 + 1];
    float v[8];
    v[0] = (a.x - mean) * rstd * g0.x + c0.x;
    v[1] = (a.y - mean) * rstd * g0.y + c0.y;
    v[2] = (a.z - mean) * rstd * g0.z + c0.z;
    v[3] = (a.w - mean) * rstd * g0.w + c0.w;
    v[4] = (b.x - mean) * rstd * g1.x + c1.x;
    v[5] = (b.y - mean) * rstd * g1.y + c1.y;
    v[6] = (b.z - mean) * rstd * g1.z + c1.z;
    v[7] = (b.w - mean) * rstd * g1.w + c1.w;
    {
        uint32_t base = (uint32_t)w * (DD / 2) + (lane >> 1) * 8 + (lane & 1);
        split8_scatter(g_hhi + base, g_hlo + base, v);
    }

    if (PROJ) {
        float acc8[8];
#pragma unroll
        for (int t = 0; t < 8; ++t) acc8[t] = 0.f;
        int f0 = lane * 8;
#pragma unroll
        for (int j = 0; j < 8; ++j) {
            int f = f0 + j;
            float x = v[j];
            float2 wir = *(const float2*)&Wir[f * 2];
            float2 wor = *(const float2*)&Wor[f * 2];
            float2 wia = *(const float2*)&Wia[f * 2];
            float2 woa = *(const float2*)&Woa[f * 2];
            acc8[0] += x * wir.x; acc8[1] += x * wir.y;
            acc8[2] += x * wor.x; acc8[3] += x * wor.y;
            acc8[4] += x * wia.x; acc8[5] += x * wia.y;
            acc8[6] += x * woa.x; acc8[7] += x * woa.y;
        }
#pragma unroll
        for (int o = 16; o; o >>= 1)
#pragma unroll
            for (int t = 0; t < 8; ++t)
                acc8[t] += __shfl_xor_sync(0xffffffffu, acc8[t], o);
        if (lane == 0) {
            *(float4*)&g_r4[w * 4] = make_float4(acc8[0], acc8[1], acc8[2], acc8[3]);
            *(float4*)&g_z4[w * 4] = make_float4(acc8[4], acc8[5], acc8[6], acc8[7]);
        }
    }
}

// ---------------- gates (+ warp-aggregated compaction) ------------------------
// forward-exact reduction of hard gumbel-softmax: gate = argmax(logits+g);
// per-node temperature is argmax-invariant; straight-through == hard fwd.
__global__ void k_gates(const float* __restrict__ bi, const float* __restrict__ bo,
                        const float* __restrict__ gum) {
    int i = blockIdx.x * blockDim.x + threadIdx.x;
    bool valid = (i < NN);
    int gi = 0;
    if (valid) {
        float4 rr = *(const float4*)&g_r4[i * 4];
        float sx = 0.f, sy = 0.f, sz = 0.f, sw = 0.f;
        int beg = g_rowptr[i], end = g_rowptr[i + 1];
        for (int p = beg; p < end; ++p) {
            int v = g_col[p];
            float4 z = *(const float4*)&g_z4[v * 4];
            sx += z.x; sy += z.y; sz += z.z; sw += z.w;
        }
        float in0 = rr.x + sx + bi[0] + gum[i * 2 + 0];
        float in1 = rr.y + sy + bi[1] + gum[i * 2 + 1];
        float ot0 = rr.z + sz + bo[0] + gum[2 * NN + i * 2 + 0];
        float ot1 = rr.w + sw + bo[1] + gum[2 * NN + i * 2 + 1];
        gi = (in0 >= in1) ? 1 : 0;
        g_gin[i] = (unsigned char)gi;
        g_gout[i] = (ot0 >= ot1) ? 1 : 0;
    }
    unsigned m = __ballot_sync(0xffffffffu, valid && gi);
    if (m) {
        int lane = threadIdx.x & 31;
        int leader = __ffs(m) - 1;
        int base = 0;
        if (lane == leader) base = atomicAdd(&g_nact, __popc(m));
        base = __shfl_sync(0xffffffffu, base, leader);
        if (valid && gi) {
            int j = base + __popc(m & ((1u << lane) - 1));
            g_list[j] = i;
            g_pos[i] = j;
        }
    }
}

// ---------------- compacted gated aggregation (plane gather, in-layout) ------
// Sums hi+lo reconstructions word-wise (layout permutation commutes with sum),
// re-splits the fp32 sums into hi/lo planes for the agg GEMM.
__global__ void k_agg_c() {
    int j = (blockIdx.x * blockDim.x + threadIdx.x) >> 5;
    int lane = threadIdx.x & 31;
    if (j >= g_nact) return;
    int node = g_list[j];
    float av[8] = {0.f, 0.f, 0.f, 0.f, 0.f, 0.f, 0.f, 0.f};
    int beg = g_rowptr[node], end = g_rowptr[node + 1];
    for (int p = beg; p < end; ++p) {
        int v = g_col[p];
        if (!g_gout[v]) continue;
        size_t base = (size_t)v * (DD / 2) + lane * 4;
        uint4 h = *(const uint4*)(g_hhi + base);
        uint4 l = *(const uint4*)(g_hlo + base);
        const uint32_t hw[4] = {h.x, h.y, h.z, h.w};
        const uint32_t lw[4] = {l.x, l.y, l.z, l.w};
#pragma unroll
        for (int t = 0; t < 4; ++t) {
            float2 hf = __half22float2(*(const __half2*)&hw[t]);
            float2 lf = __half22float2(*(const __half2*)&lw[t]);
            av[2 * t] += hf.x + lf.x;
            av[2 * t + 1] += hf.y + lf.y;
        }
    }
    uint32_t ho[4], lo[4];
#pragma unroll
    for (int t = 0; t < 4; ++t) {
        float ra, rb;
        ho[t] = pack_h2(av[2 * t], av[2 * t + 1], ra, rb);
        lo[t] = pack_h2r(ra, rb);
    }
    size_t base = (size_t)j * (DD / 2) + lane * 4;
    *(uint4*)(g_ahi + base) = make_uint4(ho[0], ho[1], ho[2], ho[3]);
    *(uint4*)(g_alo + base) = make_uint4(lo[0], lo[1], lo[2], lo[3]);
}

// ---------------- cp.async fp16-split GEMM ------------------------------------
// EPI: 0 = relu+bias (enc), 1 = bias only (dec),
//      2 = root: bias + (gin ? tmp[pos[r]] : 0), relu, store ph
//      3 = compact agg (M=g_nact): plain store to tmp, no bias/relu
// 4-stage cp.async pipeline; stage = 3072 words: Ahi[0,1024) Alo[1024,2048)
// Bhi[2048,2560) Blo[2560,3072). A word idx in stage: r*8 + w; B: n*8 + w.
template <int EPI>
__global__ __launch_bounds__(256, 2) void k_mma(
    const uint32_t* __restrict__ Ahi, const uint32_t* __restrict__ Alo, int K,
    const uint32_t* __restrict__ Bhi, const uint32_t* __restrict__ Blo,
    const float* __restrict__ bias, float* __restrict__ C, int Mparam, int Nc) {
    __shared__ __align__(16) uint32_t sm[12288];  // 4 stages x 3072
    const int M = (EPI == 3) ? g_nact : Mparam;
    const int rowBase = blockIdx.y * 128;
    if (rowBase >= M) return;
    const int tid = threadIdx.x;
    const int warp = tid >> 5, lane = tid & 31;
    const int gid = lane >> 2, tig = lane & 3;
    const int wm = warp >> 1, wn = warp & 1;
    const int cb = blockIdx.x, colBase = cb * 64;
    const int nT = K >> 4;
    const int Kw = K >> 1;  // words per A row

    float acc[2][4][4];
#pragma unroll
    for (int i = 0; i < 2; ++i)
#pragma unroll
        for (int j = 0; j < 4; ++j)
#pragma unroll
            for (int q = 0; q < 4; ++q) acc[i][j][q] = 0.f;

    // cp.async roles
    const int aR = tid >> 1, hf = tid & 1;
    const int r0 = rowBase + aR;
    const int rc = (r0 < M) ? r0 : (M - 1);
    const uint32_t* gAh = Ahi + (size_t)rc * Kw + hf * 4;
    const uint32_t* gAl = Alo + (size_t)rc * Kw + hf * 4;
    const int szA = (r0 < M) ? 16 : 0;
    const int bc = tid & 127;
    const bool blo = (tid >= 128);
    const uint32_t* gB = (blo ? Blo : Bhi) + (size_t)cb * nT * 512 + bc * 4;
    const uint32_t smb = smem_u32(sm);
    const uint32_t dA0 = smb + (aR * 8 + hf * 4) * 4;
    const uint32_t dA1 = dA0 + 4096;
    const uint32_t dB = smb + (2048 + (blo ? 512 : 0) + bc * 4) * 4;

    auto issue = [&](int t) {
        uint32_t off = (uint32_t)(t & 3) * 12288;
        cp16(dA0 + off, gAh + (size_t)t * 8, szA);
        cp16(dA1 + off, gAl + (size_t)t * 8, szA);
        cp16(dB + off, gB + (size_t)t * 512, 16);
        cp_commit();
    };

    issue(0);
    if (nT > 1) issue(1);
    if (nT > 2) issue(2);

    for (int t = 0; t < nT; ++t) {
        cp_wait2();
        __syncthreads();
        if (t + 3 < nT) issue(t + 3);
        const uint32_t* S = sm + (t & 3) * 3072;
        uint2 ah[2][2], al[2][2], bh[4], bl[4];
#pragma unroll
        for (int mt = 0; mt < 2; ++mt) {
            int r = wm * 32 + mt * 16 + gid;
            ah[mt][0] = *(const uint2*)&S[r * 8 + tig * 2];
            ah[mt][1] = *(const uint2*)&S[(r + 8) * 8 + tig * 2];
            al[mt][0] = *(const uint2*)&S[1024 + r * 8 + tig * 2];
            al[mt][1] = *(const uint2*)&S[1024 + (r + 8) * 8 + tig * 2];
        }
#pragma unroll
        for (int nt = 0; nt < 4; ++nt) {
            int n = wn * 32 + nt * 8 + gid;
            bh[nt] = *(const uint2*)&S[2048 + n * 8 + tig * 2];
            bl[nt] = *(const uint2*)&S[2560 + n * 8 + tig * 2];
        }
        // 3 passes of 8 independent MMAs (break RAW chains per accumulator)
#pragma unroll
        for (int mt = 0; mt < 2; ++mt)
#pragma unroll
            for (int nt = 0; nt < 4; ++nt)
                mma16816(acc[mt][nt], ah[mt][0].x, ah[mt][1].x, ah[mt][0].y,
                         ah[mt][1].y, bh[nt].x, bh[nt].y);
#pragma unroll
        for (int mt = 0; mt < 2; ++mt)
#pragma unroll
            for (int nt = 0; nt < 4; ++nt)
                mma16816(acc[mt][nt], al[mt][0].x, al[mt][1].x, al[mt][0].y,
                         al[mt][1].y, bh[nt].x, bh[nt].y);
#pragma unroll
        for (int mt = 0; mt < 2; ++mt)
#pragma unroll
            for (int nt = 0; nt < 4; ++nt)
                mma16816(acc[mt][nt], ah[mt][0].x, ah[mt][1].x, ah[mt][0].y,
                         ah[mt][1].y, bl[nt].x, bl[nt].y);
        __syncthreads();
    }

#pragma unroll
    for (int mt = 0; mt < 2; ++mt) {
        int rr = rowBase + wm * 32 + mt * 16 + gid;
#pragma unroll
        for (int nt = 0; nt < 4; ++nt) {
            int col = colBase + wn * 32 + nt * 8 + tig * 2;
            float* a = acc[mt][nt];
#pragma unroll
            for (int h = 0; h < 2; ++h) {
                int r = rr + h * 8;
                if (r >= M) continue;
                float2 o = make_float2(a[h * 2 + 0], a[h * 2 + 1]);
                if (EPI == 3) {
                    *(float2*)(C + (size_t)r * Nc + col) = o;
                    continue;
                }
                float2 bv = *(const float2*)(bias + col);
                o.x += bv.x;
                o.y += bv.y;
                if (EPI == 0) {
                    o.x = fmaxf(o.x, 0.f);
                    o.y = fmaxf(o.y, 0.f);
                } else if (EPI == 2) {
                    if (g_gin[r]) {
                        float2 tv = *(const float2*)(g_tmp +
                                                     (size_t)g_pos[r] * Nc + col);
                        o.x += tv.x;
                        o.y += tv.y;
                    }
                    o.x = fmaxf(o.x, 0.f);
                    o.y = fmaxf(o.y, 0.f);
                }
                *(float2*)(C + (size_t)r * Nc + col) = o;
            }
        }
    }
}

// ---------------- launch -----------------------------------------------------
extern "C" void kernel_launch(void* const* d_in, const int* in_sizes, int n_in,
                              void* d_out, int out_size) {
    const float* x = (const float*)d_in[0];
    const int* ei = (const int*)d_in[1];
    const float* gum = (const float*)d_in[2];
    const float* W_enc = (const float*)d_in[3];
    const float* b_enc = (const float*)d_in[4];
    const float* W_root = (const float*)d_in[5];
    const float* W_agg = (const float*)d_in[6];
    const float* b_env = (const float*)d_in[7];
    const float* Wir = (const float*)d_in[8];
    const float* Wia = (const float*)d_in[9];
    const float* bi = (const float*)d_in[10];
    const float* Wor = (const float*)d_in[11];
    const float* Woa = (const float*)d_in[12];
    const float* bo = (const float*)d_in[13];
    // d_in[14..16] = temperature net: forward-dead (argmax is temp-invariant)
    const float* ln_g = (const float*)d_in[17];
    const float* ln_b = (const float*)d_in[18];
    const float* W_dec = (const float*)d_in[19];
    const float* b_dec = (const float*)d_in[20];
    float* out = (float*)d_out;

    float *ph, *ptmp;
    uint32_t *xhi, *xlo, *hhi, *hlo, *ahi, *alo, *whi, *wlo;
    cudaGetSymbolAddress((void**)&ph, g_h);
    cudaGetSymbolAddress((void**)&ptmp, g_tmp);
    cudaGetSymbolAddress((void**)&xhi, g_xhi);
    cudaGetSymbolAddress((void**)&xlo, g_xlo);
    cudaGetSymbolAddress((void**)&hhi, g_hhi);
    cudaGetSymbolAddress((void**)&hlo, g_hlo);
    cudaGetSymbolAddress((void**)&ahi, g_ahi);
    cudaGetSymbolAddress((void**)&alo, g_alo);
    cudaGetSymbolAddress((void**)&whi, g_whi);
    cudaGetSymbolAddress((void**)&wlo, g_wlo);

    int wgrid = (NN * 32 + 255) / 256;
    int ngrid = (NN + 255) / 256;
    dim3 gMain(DD / 64, (NN + 127) / 128);   // 4 x 391
    dim3 gDec(DOUT / 64, (NN + 127) / 128);  // 1 x 391

    // CSR build (edge_index is a fresh input each call)
    k_zero_cnt<<<ngrid, 256>>>();
    k_hist<<<(EE + 255) / 256, 256>>>(ei);
    k_scan<<<1, 1024>>>();
    k_scatter<<<(EE + 255) / 256, 256>>>(ei);

    // pack weights + x into split-plane images
    k_pack_w<<<(IMG_TOT + 255) / 256, 256>>>(W_enc, W_root, W_agg, W_dec);
    k_pack_x<<<(NN * DIN / 8 + 255) / 256, 256>>>(x);

    // encoder: h = relu(x @ W_enc + b_enc)
    k_mma<0><<<gMain, 256>>>(xhi, xlo, DIN, whi + IMG_ENC, wlo + IMG_ENC,
                             b_enc, ph, NN, DD);

    for (int l = 0; l < 3; ++l) {
        k_ln<true><<<wgrid, 256>>>(ph, ln_g, ln_b, Wir, Wia, Wor, Woa);
        k_gates<<<ngrid, 256>>>(bi, bo, gum + (size_t)l * 2 * NN * 2);
        k_agg_c<<<wgrid, 256>>>();
        // agg GEMM first (compact rows -> tmp)
        k_mma<3><<<gMain, 256>>>(ahi, alo, DD, whi + IMG_AGG(l),
                                 wlo + IMG_AGG(l), nullptr, ptmp, 0, DD);
        // root GEMM (adds tmp for gin rows, relu, writes ph)
        k_mma<2><<<gMain, 256>>>(hhi, hlo, DD, whi + IMG_ROOT(l),
                                 wlo + IMG_ROOT(l), b_env + (size_t)l * DD,
                                 ph, NN, DD);
    }

    k_ln<false><<<wgrid, 256>>>(ph, ln_g, ln_b, nullptr, nullptr, nullptr, nullptr);
    k_mma<1><<<gDec, 256>>>(hhi, hlo, DD, whi + IMG_DEC, wlo + IMG_DEC,
                            b_dec, out, NN, DOUT);
}

// round 16
// speedup vs baseline: 2.4505x; 1.1743x over previous
#include <cuda_runtime.h>
#include <cuda_fp16.h>
#include <cstdint>

#define NN   50000
#define EE   800000
#define DIN  128
#define DD   256
#define DOUT 64

// ---------------- scratch (device globals) ----------------------------------
__device__ __align__(16) float g_h[NN * DD];
__device__ __align__(16) float g_tmp[NN * DD];   // compact agg GEMM output
__device__ __align__(16) float g_r4[NN * 4];
__device__ __align__(16) float g_z4[NN * 4];
// fp16 split planes, stored as uint32 (half2) words in the GEMM smem image
// layout: per row, per 16-k tile, 8 words; word w = 2t + kh holds halves
// {k = kt*16 + kh*8 + 2t, k+1}.
__device__ __align__(16) uint32_t g_xhi[NN * DIN / 2];
__device__ __align__(16) uint32_t g_xlo[NN * DIN / 2];
__device__ __align__(16) uint32_t g_hhi[NN * DD / 2];
__device__ __align__(16) uint32_t g_hlo[NN * DD / 2];
__device__ __align__(16) uint32_t g_ahi[NN * DD / 2];  // compacted agg rows
__device__ __align__(16) uint32_t g_alo[NN * DD / 2];
// W images: [cb][kt][n(64)][8 words], same word interleave, B[n][k]=W[k][n]
#define IMG_ENC 0
#define IMG_ROOT(l) (16384 + (l) * 32768)
#define IMG_AGG(l)  (114688 + (l) * 32768)
#define IMG_DEC 212992
#define IMG_TOT 221184
__device__ __align__(16) uint32_t g_whi[IMG_TOT];
__device__ __align__(16) uint32_t g_wlo[IMG_TOT];
// CSR + gates
__device__ int g_rowptr[NN + 1];
__device__ int g_cnt[NN];
__device__ int g_fill[NN];
__device__ int g_col[EE];
__device__ unsigned char g_gin[NN];
__device__ unsigned char g_gout[NN];
__device__ int g_nact;
__device__ int g_list[NN];
__device__ int g_pos[NN];   // node -> compact row (valid when gin)

// ---------------- helpers -----------------------------------------------------
__device__ __forceinline__ uint32_t pack_h2(float a, float b, float& ra, float& rb) {
    __half ha = __float2half_rn(a), hb = __float2half_rn(b);
    ra = a - __half2float(ha);
    rb = b - __half2float(hb);
    __half2 h = __halves2half2(ha, hb);
    return *(uint32_t*)&h;
}
__device__ __forceinline__ uint32_t pack_h2r(float a, float b) {
    __half2 h = __halves2half2(__float2half_rn(a), __float2half_rn(b));
    return *(uint32_t*)&h;
}
// 8 consecutive k-values of one row -> 4 hi + 4 lo words at stride 2
__device__ __forceinline__ void split8_scatter(uint32_t* hp, uint32_t* lp,
                                               const float* v) {
#pragma unroll
    for (int t = 0; t < 4; ++t) {
        float ra, rb;
        hp[t * 2] = pack_h2(v[2 * t], v[2 * t + 1], ra, rb);
        lp[t * 2] = pack_h2r(ra, rb);
    }
}

__device__ __forceinline__ void mma16816(float* c, uint32_t a0, uint32_t a1,
                                         uint32_t a2, uint32_t a3,
                                         uint32_t b0, uint32_t b1) {
    asm volatile(
        "mma.sync.aligned.m16n8k16.row.col.f32.f16.f16.f32 "
        "{%0,%1,%2,%3}, {%4,%5,%6,%7}, {%8,%9}, {%0,%1,%2,%3};"
        : "+f"(c[0]), "+f"(c[1]), "+f"(c[2]), "+f"(c[3])
        : "r"(a0), "r"(a1), "r"(a2), "r"(a3), "r"(b0), "r"(b1));
}

__device__ __forceinline__ uint32_t smem_u32(const void* p) {
    uint32_t a;
    asm("{ .reg .u64 t; cvta.to.shared.u64 t, %1; cvt.u32.u64 %0, t; }"
        : "=r"(a) : "l"(p));
    return a;
}
__device__ __forceinline__ void cp16(uint32_t dst, const void* src, int sz) {
    asm volatile("cp.async.cg.shared.global [%0], [%1], 16, %2;"
                 :: "r"(dst), "l"(src), "r"(sz) : "memory");
}
__device__ __forceinline__ void cp_commit() {
    asm volatile("cp.async.commit_group;" ::: "memory");
}
__device__ __forceinline__ void cp_wait2() {
    asm volatile("cp.async.wait_group 2;" ::: "memory");
}

// ---------------- CSR build --------------------------------------------------
__global__ void k_zero_cnt() {
    int i = blockIdx.x * blockDim.x + threadIdx.x;
    if (i < NN) g_cnt[i] = 0;
}
__global__ void k_hist(const int* __restrict__ ei) {
    int e = blockIdx.x * blockDim.x + threadIdx.x;
    if (e < EE) atomicAdd(&g_cnt[ei[e]], 1);
}
__global__ void k_scan() {
    __shared__ int sh[1024];
    int t = threadIdx.x;
    const int CH = (NN + 1023) / 1024;
    int s0 = t * CH;
    int s = 0;
    for (int i = 0; i < CH; ++i) {
        int idx = s0 + i;
        if (idx < NN) s += g_cnt[idx];
    }
    sh[t] = s;
    __syncthreads();
    for (int off = 1; off < 1024; off <<= 1) {
        int tmp = (t >= off) ? sh[t - off] : 0;
        __syncthreads();
        sh[t] += tmp;
        __syncthreads();
    }
    int run = sh[t] - s;
    for (int i = 0; i < CH; ++i) {
        int idx = s0 + i;
        if (idx < NN) {
            g_rowptr[idx] = run;
            run += g_cnt[idx];
            g_fill[idx] = 0;
        }
    }
    if (t == 0) g_rowptr[NN] = EE;
}
__global__ void k_scatter(const int* __restrict__ ei) {
    int e = blockIdx.x * blockDim.x + threadIdx.x;
    if (e < EE) {
        int u = ei[e];
        int v = ei[EE + e];
        int pos = g_rowptr[u] + atomicAdd(&g_fill[u], 1);
        g_col[pos] = v;
    }
}

// ---------------- packing ------------------------------------------------------
__global__ void k_pack_x(const float* __restrict__ x) {
    int i = blockIdx.x * blockDim.x + threadIdx.x;  // octet index
    if (i >= NN * DIN / 8) return;
    int r = i >> 4, oct = i & 15;
    int kt = oct >> 1, kh = oct & 1;
    const float4* p = (const float4*)(x + (size_t)r * DIN + oct * 8);
    float4 a = p[0], b = p[1];
    float v[8] = {a.x, a.y, a.z, a.w, b.x, b.y, b.z, b.w};
    uint32_t base = (uint32_t)r * (DIN / 2) + kt * 8 + kh;
    split8_scatter(g_xhi + base, g_xlo + base, v);
}

// all weight images in one kernel
__global__ void k_pack_w(const float* __restrict__ Wenc,
                         const float* __restrict__ Wroot,
                         const float* __restrict__ Wagg,
                         const float* __restrict__ Wdec) {
    int i = blockIdx.x * blockDim.x + threadIdx.x;
    if (i >= IMG_TOT) return;
    const float* W;
    int li, K, N;
    if (i < 16384) { W = Wenc; li = i; K = DIN; N = DD; }
    else if (i < 114688) {
        int j = i - 16384;
        W = Wroot + (size_t)(j / 32768) * DD * DD;
        li = j % 32768; K = DD; N = DD;
    } else if (i < 212992) {
        int j = i - 114688;
        W = Wagg + (size_t)(j / 32768) * DD * DD;
        li = j % 32768; K = DD; N = DD;
    } else { W = Wdec; li = i - 212992; K = DD; N = DOUT; }
    int w = li & 7, n = (li >> 3) & 63, rest = li >> 9;
    int nKt = K >> 4;
    int kt = rest % nKt, cb = rest / nKt;
    int t = w >> 1, kh = w & 1;
    int k0 = kt * 16 + kh * 8 + 2 * t;
    int ng = cb * 64 + n;
    float v0 = W[(size_t)k0 * N + ng];
    float v1 = W[(size_t)(k0 + 1) * N + ng];
    float ra, rb;
    g_whi[i] = pack_h2(v0, v1, ra, rb);
    g_wlo[i] = pack_h2r(ra, rb);
}

// ---------------- LayerNorm (+ proj, + deferred agg-add/relu) -----------------
// FUSE: input row = relu(h + (gin ? tmp[pos] : 0))  (conv epilogue moved here)
template <bool PROJ, bool FUSE>
__global__ void k_ln(const float* __restrict__ in,
                     const float* __restrict__ gam, const float* __restrict__ bet,
                     const float* __restrict__ Wir, const float* __restrict__ Wia,
                     const float* __restrict__ Wor, const float* __restrict__ Woa) {
    if (PROJ && blockIdx.x == 0 && threadIdx.x == 0) g_nact = 0;
    int w = (blockIdx.x * blockDim.x + threadIdx.x) >> 5;
    int lane = threadIdx.x & 31;
    if (w >= NN) return;
    const float4* r = (const float4*)(in + (size_t)w * DD);
    float4 a = r[lane * 2], b = r[lane * 2 + 1];
    if (FUSE) {
        if (g_gin[w]) {
            const float4* tr = (const float4*)(g_tmp + (size_t)g_pos[w] * DD);
            float4 t0 = tr[lane * 2], t1 = tr[lane * 2 + 1];
            a.x += t0.x; a.y += t0.y; a.z += t0.z; a.w += t0.w;
            b.x += t1.x; b.y += t1.y; b.z += t1.z; b.w += t1.w;
        }
        a.x = fmaxf(a.x, 0.f); a.y = fmaxf(a.y, 0.f);
        a.z = fmaxf(a.z, 0.f); a.w = fmaxf(a.w, 0.f);
        b.x = fmaxf(b.x, 0.f); b.y = fmaxf(b.y, 0.f);
        b.z = fmaxf(b.z, 0.f); b.w = fmaxf(b.w, 0.f);
    }
    float s = a.x + a.y + a.z + a.w + b.x + b.y + b.z + b.w;
#pragma unroll
    for (int o = 16; o; o >>= 1) s += __shfl_xor_sync(0xffffffffu, s, o);
    float mean = s * (1.0f / DD);
    float d, sq = 0.f;
    d = a.x - mean; sq += d * d; d = a.y - mean; sq += d * d;
    d = a.z - mean; sq += d * d; d = a.w - mean; sq += d * d;
    d = b.x - mean; sq += d * d; d = b.y - mean; sq += d * d;
    d = b.z - mean; sq += d * d; d = b.w - mean; sq += d * d;
#pragma unroll
    for (int o = 16; o; o >>= 1) sq += __shfl_xor_sync(0xffffffffu, sq, o);
    float rstd = rsqrtf(sq * (1.0f / DD) + 1e-5f);
    const float4* g4 = (const float4*)gam;
    const float4* b4 = (const float4*)bet;
    float4 g0 = g4[lane * 2], g1 = g4[lane * 2 + 1];
    float4 c0 = b4[lane * 2], c1 = b4[lane * 2 + 1];
    float v[8];
    v[0] = (a.x - mean) * rstd * g0.x + c0.x;
    v[1] = (a.y - mean) * rstd * g0.y + c0.y;
    v[2] = (a.z - mean) * rstd * g0.z + c0.z;
    v[3] = (a.w - mean) * rstd * g0.w + c0.w;
    v[4] = (b.x - mean) * rstd * g1.x + c1.x;
    v[5] = (b.y - mean) * rstd * g1.y + c1.y;
    v[6] = (b.z - mean) * rstd * g1.z + c1.z;
    v[7] = (b.w - mean) * rstd * g1.w + c1.w;
    {
        uint32_t base = (uint32_t)w * (DD / 2) + (lane >> 1) * 8 + (lane & 1);
        split8_scatter(g_hhi + base, g_hlo + base, v);
    }

    if (PROJ) {
        float acc8[8];
#pragma unroll
        for (int t = 0; t < 8; ++t) acc8[t] = 0.f;
        int f0 = lane * 8;
#pragma unroll
        for (int j = 0; j < 8; ++j) {
            int f = f0 + j;
            float x = v[j];
            float2 wir = *(const float2*)&Wir[f * 2];
            float2 wor = *(const float2*)&Wor[f * 2];
            float2 wia = *(const float2*)&Wia[f * 2];
            float2 woa = *(const float2*)&Woa[f * 2];
            acc8[0] += x * wir.x; acc8[1] += x * wir.y;
            acc8[2] += x * wor.x; acc8[3] += x * wor.y;
            acc8[4] += x * wia.x; acc8[5] += x * wia.y;
            acc8[6] += x * woa.x; acc8[7] += x * woa.y;
        }
#pragma unroll
        for (int o = 16; o; o >>= 1)
#pragma unroll
            for (int t = 0; t < 8; ++t)
                acc8[t] += __shfl_xor_sync(0xffffffffu, acc8[t], o);
        if (lane == 0) {
            *(float4*)&g_r4[w * 4] = make_float4(acc8[0], acc8[1], acc8[2], acc8[3]);
            *(float4*)&g_z4[w * 4] = make_float4(acc8[4], acc8[5], acc8[6], acc8[7]);
        }
    }
}

// ---------------- gates (+ warp-aggregated compaction) ------------------------
// forward-exact reduction of hard gumbel-softmax: gate = argmax(logits+g);
// per-node temperature is argmax-invariant; straight-through == hard fwd.
__global__ void k_gates(const float* __restrict__ bi, const float* __restrict__ bo,
                        const float* __restrict__ gum) {
    int i = blockIdx.x * blockDim.x + threadIdx.x;
    bool valid = (i < NN);
    int gi = 0;
    if (valid) {
        float4 rr = *(const float4*)&g_r4[i * 4];
        float sx = 0.f, sy = 0.f, sz = 0.f, sw = 0.f;
        int beg = g_rowptr[i], end = g_rowptr[i + 1];
        for (int p = beg; p < end; ++p) {
            int v = g_col[p];
            float4 z = *(const float4*)&g_z4[v * 4];
            sx += z.x; sy += z.y; sz += z.z; sw += z.w;
        }
        float in0 = rr.x + sx + bi[0] + gum[i * 2 + 0];
        float in1 = rr.y + sy + bi[1] + gum[i * 2 + 1];
        float ot0 = rr.z + sz + bo[0] + gum[2 * NN + i * 2 + 0];
        float ot1 = rr.w + sw + bo[1] + gum[2 * NN + i * 2 + 1];
        gi = (in0 >= in1) ? 1 : 0;
        g_gin[i] = (unsigned char)gi;
        g_gout[i] = (ot0 >= ot1) ? 1 : 0;
    }
    unsigned m = __ballot_sync(0xffffffffu, valid && gi);
    if (m) {
        int lane = threadIdx.x & 31;
        int leader = __ffs(m) - 1;
        int base = 0;
        if (lane == leader) base = atomicAdd(&g_nact, __popc(m));
        base = __shfl_sync(0xffffffffu, base, leader);
        if (valid && gi) {
            int j = base + __popc(m & ((1u << lane) - 1));
            g_list[j] = i;
            g_pos[i] = j;
        }
    }
}

// ---------------- compacted gated aggregation (plane gather, in-layout) ------
// Sums hi+lo reconstructions word-wise (layout permutation commutes with sum),
// re-splits the fp32 sums into hi/lo planes for the agg GEMM.
__global__ void k_agg_c() {
    int j = (blockIdx.x * blockDim.x + threadIdx.x) >> 5;
    int lane = threadIdx.x & 31;
    if (j >= g_nact) return;
    int node = g_list[j];
    float av[8] = {0.f, 0.f, 0.f, 0.f, 0.f, 0.f, 0.f, 0.f};
    int beg = g_rowptr[node], end = g_rowptr[node + 1];
    for (int p = beg; p < end; ++p) {
        int v = g_col[p];
        if (!g_gout[v]) continue;
        size_t base = (size_t)v * (DD / 2) + lane * 4;
        uint4 h = *(const uint4*)(g_hhi + base);
        uint4 l = *(const uint4*)(g_hlo + base);
        const uint32_t hw[4] = {h.x, h.y, h.z, h.w};
        const uint32_t lw[4] = {l.x, l.y, l.z, l.w};
#pragma unroll
        for (int t = 0; t < 4; ++t) {
            float2 hf = __half22float2(*(const __half2*)&hw[t]);
            float2 lf = __half22float2(*(const __half2*)&lw[t]);
            av[2 * t] += hf.x + lf.x;
            av[2 * t + 1] += hf.y + lf.y;
        }
    }
    uint32_t ho[4], lo[4];
#pragma unroll
    for (int t = 0; t < 4; ++t) {
        float ra, rb;
        ho[t] = pack_h2(av[2 * t], av[2 * t + 1], ra, rb);
        lo[t] = pack_h2r(ra, rb);
    }
    size_t base = (size_t)j * (DD / 2) + lane * 4;
    *(uint4*)(g_ahi + base) = make_uint4(ho[0], ho[1], ho[2], ho[3]);
    *(uint4*)(g_alo + base) = make_uint4(lo[0], lo[1], lo[2], lo[3]);
}

// ---------------- cp.async fp16-split GEMM ------------------------------------
// EPI: 0 = bias+relu (enc), 1 = bias only (root, dec),
//      3 = compact agg (M=g_nact): plain store, no bias/relu
// 4-stage cp.async pipeline; stage = 3072 words: Ahi[0,1024) Alo[1024,2048)
// Bhi[2048,2560) Blo[2560,3072). A word idx in stage: r*8 + w; B: n*8 + w.
template <int EPI>
__global__ __launch_bounds__(256, 2) void k_mma(
    const uint32_t* __restrict__ Ahi, const uint32_t* __restrict__ Alo, int K,
    const uint32_t* __restrict__ Bhi, const uint32_t* __restrict__ Blo,
    const float* __restrict__ bias, float* __restrict__ C, int Mparam, int Nc) {
    __shared__ __align__(16) uint32_t sm[12288];  // 4 stages x 3072
    const int M = (EPI == 3) ? g_nact : Mparam;
    const int rowBase = blockIdx.y * 128;
    if (rowBase >= M) return;
    const int tid = threadIdx.x;
    const int warp = tid >> 5, lane = tid & 31;
    const int gid = lane >> 2, tig = lane & 3;
    const int wm = warp >> 1, wn = warp & 1;
    const int cb = blockIdx.x, colBase = cb * 64;
    const int nT = K >> 4;
    const int Kw = K >> 1;  // words per A row

    float acc[2][4][4];
#pragma unroll
    for (int i = 0; i < 2; ++i)
#pragma unroll
        for (int j = 0; j < 4; ++j)
#pragma unroll
            for (int q = 0; q < 4; ++q) acc[i][j][q] = 0.f;

    // cp.async roles
    const int aR = tid >> 1, hf = tid & 1;
    const int r0 = rowBase + aR;
    const int rc = (r0 < M) ? r0 : (M - 1);
    const uint32_t* gAh = Ahi + (size_t)rc * Kw + hf * 4;
    const uint32_t* gAl = Alo + (size_t)rc * Kw + hf * 4;
    const int szA = (r0 < M) ? 16 : 0;
    const int bc = tid & 127;
    const bool blo = (tid >= 128);
    const uint32_t* gB = (blo ? Blo : Bhi) + (size_t)cb * nT * 512 + bc * 4;
    const uint32_t smb = smem_u32(sm);
    const uint32_t dA0 = smb + (aR * 8 + hf * 4) * 4;
    const uint32_t dA1 = dA0 + 4096;
    const uint32_t dB = smb + (2048 + (blo ? 512 : 0) + bc * 4) * 4;

    auto issue = [&](int t) {
        uint32_t off = (uint32_t)(t & 3) * 12288;
        cp16(dA0 + off, gAh + (size_t)t * 8, szA);
        cp16(dA1 + off, gAl + (size_t)t * 8, szA);
        cp16(dB + off, gB + (size_t)t * 512, 16);
        cp_commit();
    };

    issue(0);
    if (nT > 1) issue(1);
    if (nT > 2) issue(2);

    for (int t = 0; t < nT; ++t) {
        cp_wait2();
        __syncthreads();
        if (t + 3 < nT) issue(t + 3);
        const uint32_t* S = sm + (t & 3) * 3072;
        uint2 ah[2][2], al[2][2], bh[4], bl[4];
#pragma unroll
        for (int mt = 0; mt < 2; ++mt) {
            int r = wm * 32 + mt * 16 + gid;
            ah[mt][0] = *(const uint2*)&S[r * 8 + tig * 2];
            ah[mt][1] = *(const uint2*)&S[(r + 8) * 8 + tig * 2];
            al[mt][0] = *(const uint2*)&S[1024 + r * 8 + tig * 2];
            al[mt][1] = *(const uint2*)&S[1024 + (r + 8) * 8 + tig * 2];
        }
#pragma unroll
        for (int nt = 0; nt < 4; ++nt) {
            int n = wn * 32 + nt * 8 + gid;
            bh[nt] = *(const uint2*)&S[2048 + n * 8 + tig * 2];
            bl[nt] = *(const uint2*)&S[2560 + n * 8 + tig * 2];
        }
        // 3 passes of 8 independent MMAs (break RAW chains per accumulator)
#pragma unroll
        for (int mt = 0; mt < 2; ++mt)
#pragma unroll
            for (int nt = 0; nt < 4; ++nt)
                mma16816(acc[mt][nt], ah[mt][0].x, ah[mt][1].x, ah[mt][0].y,
                         ah[mt][1].y, bh[nt].x, bh[nt].y);
#pragma unroll
        for (int mt = 0; mt < 2; ++mt)
#pragma unroll
            for (int nt = 0; nt < 4; ++nt)
                mma16816(acc[mt][nt], al[mt][0].x, al[mt][1].x, al[mt][0].y,
                         al[mt][1].y, bh[nt].x, bh[nt].y);
#pragma unroll
        for (int mt = 0; mt < 2; ++mt)
#pragma unroll
            for (int nt = 0; nt < 4; ++nt)
                mma16816(acc[mt][nt], ah[mt][0].x, ah[mt][1].x, ah[mt][0].y,
                         ah[mt][1].y, bl[nt].x, bl[nt].y);
        __syncthreads();
    }

#pragma unroll
    for (int mt = 0; mt < 2; ++mt) {
        int rr = rowBase + wm * 32 + mt * 16 + gid;
#pragma unroll
        for (int nt = 0; nt < 4; ++nt) {
            int col = colBase + wn * 32 + nt * 8 + tig * 2;
            float* a = acc[mt][nt];
#pragma unroll
            for (int h = 0; h < 2; ++h) {
                int r = rr + h * 8;
                if (r >= M) continue;
                float2 o = make_float2(a[h * 2 + 0], a[h * 2 + 1]);
                if (EPI != 3) {
                    float2 bv = *(const float2*)(bias + col);
                    o.x += bv.x;
                    o.y += bv.y;
                    if (EPI == 0) {
                        o.x = fmaxf(o.x, 0.f);
                        o.y = fmaxf(o.y, 0.f);
                    }
                }
                *(float2*)(C + (size_t)r * Nc + col) = o;
            }
        }
    }
}

// ---------------- launch -----------------------------------------------------
extern "C" void kernel_launch(void* const* d_in, const int* in_sizes, int n_in,
                              void* d_out, int out_size) {
    const float* x = (const float*)d_in[0];
    const int* ei = (const int*)d_in[1];
    const float* gum = (const float*)d_in[2];
    const float* W_enc = (const float*)d_in[3];
    const float* b_enc = (const float*)d_in[4];
    const float* W_root = (const float*)d_in[5];
    const float* W_agg = (const float*)d_in[6];
    const float* b_env = (const float*)d_in[7];
    const float* Wir = (const float*)d_in[8];
    const float* Wia = (const float*)d_in[9];
    const float* bi = (const float*)d_in[10];
    const float* Wor = (const float*)d_in[11];
    const float* Woa = (const float*)d_in[12];
    const float* bo = (const float*)d_in[13];
    // d_in[14..16] = temperature net: forward-dead (argmax is temp-invariant)
    const float* ln_g = (const float*)d_in[17];
    const float* ln_b = (const float*)d_in[18];
    const float* W_dec = (const float*)d_in[19];
    const float* b_dec = (const float*)d_in[20];
    float* out = (float*)d_out;

    float *ph, *ptmp;
    uint32_t *xhi, *xlo, *hhi, *hlo, *ahi, *alo, *whi, *wlo;
    cudaGetSymbolAddress((void**)&ph, g_h);
    cudaGetSymbolAddress((void**)&ptmp, g_tmp);
    cudaGetSymbolAddress((void**)&xhi, g_xhi);
    cudaGetSymbolAddress((void**)&xlo, g_xlo);
    cudaGetSymbolAddress((void**)&hhi, g_hhi);
    cudaGetSymbolAddress((void**)&hlo, g_hlo);
    cudaGetSymbolAddress((void**)&ahi, g_ahi);
    cudaGetSymbolAddress((void**)&alo, g_alo);
    cudaGetSymbolAddress((void**)&whi, g_whi);
    cudaGetSymbolAddress((void**)&wlo, g_wlo);

    // side stream + events (created once; host-side objects, no device alloc)
    static cudaStream_t s2 = nullptr;
    static cudaEvent_t evStart, evF[3], evJ[3];
    if (!s2) {
        cudaStreamCreateWithFlags(&s2, cudaStreamNonBlocking);
        cudaEventCreateWithFlags(&evStart, cudaEventDisableTiming);
        for (int l = 0; l < 3; ++l) {
            cudaEventCreateWithFlags(&evF[l], cudaEventDisableTiming);
            cudaEventCreateWithFlags(&evJ[l], cudaEventDisableTiming);
        }
    }

    int wgrid = (NN * 32 + 255) / 256;
    int ngrid = (NN + 255) / 256;
    dim3 gMain(DD / 64, (NN + 127) / 128);   // 4 x 391
    dim3 gDec(DOUT / 64, (NN + 127) / 128);  // 1 x 391

    // --- fork: CSR build on s2, packing + encoder on stream 0 (independent) --
    cudaEventRecord(evStart, 0);
    cudaStreamWaitEvent(s2, evStart, 0);
    k_zero_cnt<<<ngrid, 256, 0, s2>>>();
    k_hist<<<(EE + 255) / 256, 256, 0, s2>>>(ei);
    k_scan<<<1, 1024, 0, s2>>>();
    k_scatter<<<(EE + 255) / 256, 256, 0, s2>>>(ei);

    k_pack_w<<<(IMG_TOT + 255) / 256, 256>>>(W_enc, W_root, W_agg, W_dec);
    k_pack_x<<<(NN * DIN / 8 + 255) / 256, 256>>>(x);
    // encoder: h = relu(x @ W_enc + b_enc)
    k_mma<0><<<gMain, 256>>>(xhi, xlo, DIN, whi + IMG_ENC, wlo + IMG_ENC,
                             b_enc, ph, NN, DD);

    for (int l = 0; l < 3; ++l) {
        // LN (l=0: enc output already relu'd; l>0: fuse agg-add + relu here)
        if (l == 0)
            k_ln<true, false><<<wgrid, 256>>>(ph, ln_g, ln_b, Wir, Wia, Wor, Woa);
        else
            k_ln<true, true><<<wgrid, 256>>>(ph, ln_g, ln_b, Wir, Wia, Wor, Woa);

        // fork: gate chain on s2, dense root GEMM on stream 0
        cudaEventRecord(evF[l], 0);
        cudaStreamWaitEvent(s2, evF[l], 0);
        k_gates<<<ngrid, 256, 0, s2>>>(bi, bo, gum + (size_t)l * 2 * NN * 2);
        k_agg_c<<<wgrid, 256, 0, s2>>>();
        k_mma<3><<<gMain, 256, 0, s2>>>(ahi, alo, DD, whi + IMG_AGG(l),
                                        wlo + IMG_AGG(l), nullptr, ptmp, 0, DD);
        cudaEventRecord(evJ[l], s2);

        // root GEMM: ph = hln @ W_root + b_env (pre-relu; add/relu in next LN)
        k_mma<1><<<gMain, 256>>>(hhi, hlo, DD, whi + IMG_ROOT(l),
                                 wlo + IMG_ROOT(l), b_env + (size_t)l * DD,
                                 ph, NN, DD);
        cudaStreamWaitEvent(0, evJ[l], 0);
    }

    k_ln<false, true><<<wgrid, 256>>>(ph, ln_g, ln_b,
                                      nullptr, nullptr, nullptr, nullptr);
    k_mma<1><<<gDec, 256>>>(hhi, hlo, DD, whi + IMG_DEC, wlo + IMG_DEC,
                            b_dec, out, NN, DOUT);
}